// round 13
// baseline (speedup 1.0000x reference)
#include <cuda_runtime.h>
#include <cuda_fp16.h>

// ---------------- problem constants ----------------
#define BB    8
#define CCH   256
#define HWP   1024
#define NO    16
#define NPAIR 256
#define NU    136
#define P2    49
#define DD    256
#define KFC   12544
#define FCH   1024

typedef unsigned long long u64;

// ---------------- scratch ----------------
__device__ float g_M[FCH * CCH];
__device__ float g_cb[FCH];
__device__ float g_Ft[BB * HWP * FCH];                 // channel-last projected features
__device__ float g_I0[BB * CCH * P2];
__device__ float g_ctx[BB * CCH * P2];
__device__ float g_KL[BB * 2 * P2 * DD];               // [img][s][pq][d]
__device__ float g_ub[BB * NU * 4];
__device__ float g_imap[BB * NU * 2 * P2];
__device__ float g_bimap[BB * NO * P2];
__device__ float g_objf[BB * NO * P2 * DD];            // [roi][pq][d]
__device__ __half g_Ah[BB * NO * 2 * P2 * DD];         // A_sub/A_obj, fp16 (25MB)
__device__ __half g_Puh[BB * NU * P2 * 768];           // pooled rel, fp16 (82MB)
__device__ __half g_Xh[(size_t)BB * NPAIR * KFC];      // relu(rel_feat), fp16 (51MB)
__device__ float g_Wp[DD * KFC];                       // Wrfc permuted
__device__ float g_Wp2[DD * KFC];                      // Wofc permuted
__device__ float g_part[8 * 2048 * 256];
__device__ float g_R[BB * NPAIR * DD];
__device__ float g_O[BB * NO * DD];
__device__ int   g_perm[BB * NU];                      // union launch order (area desc)

__device__ __forceinline__ float hat_int(float t) {
    t = fminf(1.f, fmaxf(-1.f, t));
    return (t < 0.f) ? 0.5f * (t + 1.f) * (t + 1.f) : 1.f - 0.5f * (1.f - t) * (1.f - t);
}

__device__ __forceinline__ unsigned f2tf32(float x) {
    unsigned r;
    asm("cvt.rna.tf32.f32 %0, %1;" : "=r"(r) : "f"(x));
    return r;
}

// ---- packed f32x2 helpers ----
__device__ __forceinline__ u64 pk2(float lo, float hi) {
    u64 r;
    asm("mov.b64 %0, {%1, %2};" : "=l"(r) : "f"(lo), "f"(hi));
    return r;
}
__device__ __forceinline__ u64 fma2(u64 a, u64 b, u64 c) {
    u64 d;
    asm("fma.rn.f32x2 %0, %1, %2, %3;" : "=l"(d) : "l"(a), "l"(b), "l"(c));
    return d;
}
__device__ __forceinline__ void upk2(u64 v, float& lo, float& hi) {
    asm("mov.b64 {%0, %1}, %2;" : "=f"(lo), "=f"(hi) : "l"(v));
}

// ---------------- K0: combine weights + union area-rank (extra block) ----------
__global__ void k_combine(const float* __restrict__ Wof, const float* __restrict__ Wrf,
                          const float* __restrict__ Wr, const float* __restrict__ br,
                          const float* __restrict__ objects) {
    int row = blockIdx.x;
    int c = threadIdx.x;
    if (row == 1024) {
        // rank all 1088 unions by descending window area; g_perm[rank] = bu
        __shared__ int sarea[BB * NU];
        for (int e = c; e < BB * NU; e += 256) {
            int b = e / NU, u = e - b * NU;
            int rem = u, i = 0;
            while (rem >= NO - i) { rem -= NO - i; ++i; }
            int j = i + rem;
            const float* ob = objects + b * NO * 4;
            float x0 = fminf(ob[i * 4 + 0], ob[j * 4 + 0]);
            float y0 = fminf(ob[i * 4 + 1], ob[j * 4 + 1]);
            float x1 = fmaxf(ob[i * 4 + 2], ob[j * 4 + 2]);
            float y1 = fmaxf(ob[i * 4 + 3], ob[j * 4 + 3]);
            float lox = x0 * 0.0625f, hix = x1 * 0.0625f;
            float loy = y0 * 0.0625f, hiy = y1 * 0.0625f;
            int hmin = max(0, (int)ceilf(loy - 1.f)), hmax = min(31, (int)floorf(hiy + 1.f));
            int wmin = max(0, (int)ceilf(lox - 1.f)), wmax = min(31, (int)floorf(hix + 1.f));
            sarea[e] = (hmax - hmin + 1) * (wmax - wmin + 1);
        }
        __syncthreads();
        for (int e = c; e < BB * NU; e += 256) {
            int a = sarea[e];
            int r = 0;
            for (int v = 0; v < BB * NU; ++v) {
                int bvv = sarea[v];
                r += (bvv > a) || (bvv == a && v < e);
            }
            g_perm[r] = e;
        }
        return;
    }
    if (row < 256) {
        g_M[row * CCH + c] = Wof[row * 512 + c];
        if (c == 0) g_cb[row] = 0.f;
    } else {
        int s = (row - 256) >> 8;
        int d = (row - 256) & 255;
        const float* w = Wrf + d * 896 + 512 + s * 128;
        float acc = 0.f;
        for (int k = 0; k < 128; ++k) acc += w[k] * Wr[(s * 128 + k) * CCH + c];
        g_M[row * CCH + c] = acc;
        if (c == 0) {
            float cb = 0.f;
            for (int k = 0; k < 128; ++k) cb += w[k] * br[s * 128 + k];
            g_cb[row] = cb;
        }
    }
}

// ---------------- K1: projection GEMM (transposed output), FFMA2 ---------------
__global__ __launch_bounds__(256) void k_projT(const float* __restrict__ input) {
    __shared__ float As[16][128];   // [k][n]
    __shared__ float Bs[16][128];   // [k][m]
    int b = blockIdx.z;
    const float* In = input + (size_t)b * CCH * HWP;
    float* C = g_Ft + (size_t)b * HWP * FCH;
    int m0 = blockIdx.x * 128, n0 = blockIdx.y * 128;
    int tid = threadIdx.x;
    int tx = tid & 15, ty = tid >> 4;
    int krow = tid >> 4, ncol = (tid & 15) * 8;
    int mrow = tid >> 1, kq = (tid & 1) * 8;
    const float* Apt = In + n0 + ncol;
    const float* Bpt = g_M + (size_t)(m0 + mrow) * CCH;
    float4 ra0 = *(const float4*)(Apt + (size_t)krow * HWP);
    float4 ra1 = *(const float4*)(Apt + (size_t)krow * HWP + 4);
    float4 rb0 = *(const float4*)(Bpt + kq);
    float4 rb1 = *(const float4*)(Bpt + kq + 4);
    u64 accp[8][4];
#pragma unroll
    for (int i = 0; i < 8; ++i)
#pragma unroll
        for (int jp = 0; jp < 4; ++jp) accp[i][jp] = 0ull;
    for (int k0 = 0; k0 < CCH; k0 += 16) {
        *(float4*)&As[krow][ncol] = ra0;
        *(float4*)&As[krow][ncol + 4] = ra1;
        Bs[kq + 0][mrow] = rb0.x; Bs[kq + 1][mrow] = rb0.y;
        Bs[kq + 2][mrow] = rb0.z; Bs[kq + 3][mrow] = rb0.w;
        Bs[kq + 4][mrow] = rb1.x; Bs[kq + 5][mrow] = rb1.y;
        Bs[kq + 6][mrow] = rb1.z; Bs[kq + 7][mrow] = rb1.w;
        __syncthreads();
        int kn = k0 + 16;
        if (kn < CCH) {
            ra0 = *(const float4*)(Apt + (size_t)(kn + krow) * HWP);
            ra1 = *(const float4*)(Apt + (size_t)(kn + krow) * HWP + 4);
            rb0 = *(const float4*)(Bpt + kn + kq);
            rb1 = *(const float4*)(Bpt + kn + kq + 4);
        }
#pragma unroll
        for (int kk = 0; kk < 16; ++kk) {
            float4 a0 = *(const float4*)&As[kk][ty * 8];
            float4 a1 = *(const float4*)&As[kk][ty * 8 + 4];
            ulonglong2 bv0 = *(const ulonglong2*)&Bs[kk][tx * 8];
            ulonglong2 bv1 = *(const ulonglong2*)&Bs[kk][tx * 8 + 4];
            u64 bp[4] = {bv0.x, bv0.y, bv1.x, bv1.y};
            float av[8] = {a0.x, a0.y, a0.z, a0.w, a1.x, a1.y, a1.z, a1.w};
#pragma unroll
            for (int i = 0; i < 8; ++i) {
                u64 ap = pk2(av[i], av[i]);
#pragma unroll
                for (int jp = 0; jp < 4; ++jp)
                    accp[i][jp] = fma2(ap, bp[jp], accp[i][jp]);
            }
        }
        __syncthreads();
    }
    float4 cb0 = *(const float4*)&g_cb[m0 + tx * 8];
    float4 cb1 = *(const float4*)&g_cb[m0 + tx * 8 + 4];
    float cb[8] = {cb0.x, cb0.y, cb0.z, cb0.w, cb1.x, cb1.y, cb1.z, cb1.w};
#pragma unroll
    for (int i = 0; i < 8; ++i) {
        int n = n0 + ty * 8 + i;
        float o[8];
#pragma unroll
        for (int jp = 0; jp < 4; ++jp) upk2(accp[i][jp], o[2 * jp], o[2 * jp + 1]);
#pragma unroll
        for (int j = 0; j < 8; ++j) o[j] += cb[j];
        *(float4*)&C[(size_t)n * FCH + m0 + tx * 8]     = make_float4(o[0], o[1], o[2], o[3]);
        *(float4*)&C[(size_t)n * FCH + m0 + tx * 8 + 4] = make_float4(o[4], o[5], o[6], o[7]);
    }
}

// ---------------- K3: geometry ---------------------------------------------------
__global__ void k_geom(const float* __restrict__ objects) {
    int b = blockIdx.x;
    int tid = threadIdx.x;
    const float* obj = objects + b * NO * 4;
    __shared__ float sub[NU * 4];
    if (tid < NU) {
        int rem = tid, i = 0;
        while (rem >= NO - i) { rem -= NO - i; ++i; }
        int j = i + rem;
        float x0 = fminf(obj[i * 4 + 0], obj[j * 4 + 0]);
        float y0 = fminf(obj[i * 4 + 1], obj[j * 4 + 1]);
        float x1 = fmaxf(obj[i * 4 + 2], obj[j * 4 + 2]);
        float y1 = fmaxf(obj[i * 4 + 3], obj[j * 4 + 3]);
        sub[tid * 4 + 0] = x0; sub[tid * 4 + 1] = y0; sub[tid * 4 + 2] = x1; sub[tid * 4 + 3] = y1;
        float* gu = g_ub + (b * NU + tid) * 4;
        gu[0] = x0; gu[1] = y0; gu[2] = x1; gu[3] = y1;
    }
    __syncthreads();
    int total = (NO + NU * 2) * P2;
    for (int v = tid; v < total; v += blockDim.x) {
        int m = v / P2, pq = v - (v / P2) * P2;
        int p = pq / 7, q = pq - p * 7;
        float b1x0, b1y0, b1x1, b1y1, g0x, g0y, g1x, g1y;
        float* dst;
        if (m < NO) {
            b1x0 = obj[m * 4 + 0]; b1y0 = obj[m * 4 + 1]; b1x1 = obj[m * 4 + 2]; b1y1 = obj[m * 4 + 3];
            g0x = 0.f; g0y = 0.f; g1x = 512.f; g1y = 512.f;
            dst = &g_bimap[(b * NO + m) * P2 + pq];
        } else {
            int mm = m - NO;
            int u = mm >> 1, ab = mm & 1;
            int rem = u, i = 0;
            while (rem >= NO - i) { rem -= NO - i; ++i; }
            int j = i + rem;
            int ob = ab ? j : i;
            b1x0 = obj[ob * 4 + 0]; b1y0 = obj[ob * 4 + 1]; b1x1 = obj[ob * 4 + 2]; b1y1 = obj[ob * 4 + 3];
            g0x = sub[u * 4 + 0]; g0y = sub[u * 4 + 1]; g1x = sub[u * 4 + 2]; g1y = sub[u * 4 + 3];
            dst = &g_imap[((b * NU + u) * 2 + ab) * P2 + pq];
        }
        float bw = (g1x - g0x) * (1.f / 7.f), bh = (g1y - g0y) * (1.f / 7.f);
        float gx0 = g0x + bw * (float)q, gy0 = g0y + bh * (float)p;
        float ox = fmaxf(0.f, fminf(gx0 + bw, b1x1) - fmaxf(gx0, b1x0));
        float oy = fmaxf(0.f, fminf(gy0 + bh, b1y1) - fmaxf(gy0, b1y0));
        *dst = oy * ox / fmaxf(bw * bh, 1e-8f);
    }
}

// ---------------- channel-last pooling, FFMA2; union mode uses g_perm ----------
__global__ __launch_bounds__(256, 3) void k_poolT(const float* __restrict__ boxes,
                                                  int mode, int rois_per_img,
                                                  const float* __restrict__ bof) {
    int roi = (mode == 2) ? g_perm[blockIdx.x] : blockIdx.x;
    int cg = blockIdx.y;
    int img = roi / rois_per_img;
    const float* bp = (mode == 1) ? (boxes + roi * 4) : (g_ub + roi * 4);
    float bx0 = bp[0], by0 = bp[1], bx1 = bp[2], by1 = bp[3];
    const float s16 = 0.0625f;
    float lox = bx0 * s16, hix = bx1 * s16, loy = by0 * s16, hiy = by1 * s16;
    float bwx = (hix - lox) * (1.f / 7.f), bwy = (hiy - loy) * (1.f / 7.f);
    float inv_area = 1.f / fmaxf(bwx * bwy, 1e-8f);

    __shared__ float wx7[32][8];
    __shared__ float wy7[32][8];
    int tid = threadIdx.x;
    if (tid < 64) {
        int w = tid & 31;
        bool isy = tid >= 32;
        float lo = isy ? loy : lox;
        float bwv = isy ? bwy : bwx;
        float* dst = isy ? &wy7[w][0] : &wx7[w][0];
#pragma unroll
        for (int q = 0; q < 7; ++q) {
            float s = lo + bwv * (float)q;
            dst[q] = hat_int(s + bwv - (float)w) - hat_int(s - (float)w);
        }
        dst[7] = 0.f;
    }
    __syncthreads();

    int hmin = max(0, (int)ceilf(loy - 1.f));
    int hmax = min(31, (int)floorf(hiy + 1.f));
    int wmin = max(0, (int)ceilf(lox - 1.f));
    int wmax = min(31, (int)floorf(hix + 1.f));

    int ch_off = (mode == 2) ? (256 + cg * 256) : 0;
    const float* Fp = g_Ft + (size_t)img * HWP * FCH + ch_off + tid;

    u64 acc2[7][4];
#pragma unroll
    for (int p = 0; p < 7; ++p)
#pragma unroll
        for (int k = 0; k < 4; ++k) acc2[p][k] = 0ull;

    for (int h = hmin; h <= hmax; ++h) {
        u64 tq2[4] = {0ull, 0ull, 0ull, 0ull};
        const float* Fh = Fp + (size_t)(h * 32) * FCH;
        for (int w = wmin; w <= wmax; ++w) {
            float f = Fh[(size_t)w * FCH];
            u64 ff = pk2(f, f);
            ulonglong2 wa = *(const ulonglong2*)&wx7[w][0];
            ulonglong2 wb = *(const ulonglong2*)&wx7[w][4];
            tq2[0] = fma2(ff, wa.x, tq2[0]);
            tq2[1] = fma2(ff, wa.y, tq2[1]);
            tq2[2] = fma2(ff, wb.x, tq2[2]);
            tq2[3] = fma2(ff, wb.y, tq2[3]);
        }
#pragma unroll
        for (int p = 0; p < 7; ++p) {
            float wyv = wy7[h][p];
            u64 wyp = pk2(wyv, wyv);
#pragma unroll
            for (int k = 0; k < 4; ++k) acc2[p][k] = fma2(wyp, tq2[k], acc2[p][k]);
        }
    }

    if (mode == 2) {
        __half* o = g_Puh + (size_t)roi * P2 * 768 + cg * 256 + tid;
#pragma unroll
        for (int p = 0; p < 7; ++p) {
            float aq[8];
#pragma unroll
            for (int k = 0; k < 4; ++k) upk2(acc2[p][k], aq[2 * k], aq[2 * k + 1]);
#pragma unroll
            for (int q = 0; q < 7; ++q)
                o[(size_t)(p * 7 + q) * 768] = __float2half(aq[q] * inv_area);
        }
    } else {
        const float* K = g_KL + ((size_t)(img * 2 + 0) * P2) * DD + tid;
        const float* L = g_KL + ((size_t)(img * 2 + 1) * P2) * DD + tid;
        const float* bm = g_bimap + (size_t)roi * P2;
        float bv = bof[tid];
        float* o = g_objf + (size_t)roi * P2 * DD + tid;
#pragma unroll
        for (int p = 0; p < 7; ++p) {
            float aq[8];
#pragma unroll
            for (int k = 0; k < 4; ++k) upk2(acc2[p][k], aq[2 * k], aq[2 * k + 1]);
#pragma unroll
            for (int q = 0; q < 7; ++q) {
                int pq = p * 7 + q;
                o[(size_t)pq * DD] = aq[q] * inv_area + K[(size_t)pq * DD]
                                   + L[(size_t)pq * DD] * bm[pq] + bv;
            }
        }
    }
}

// ---------------- mode-0 pool: raw input full-image box -> g_I0 ----------------
__global__ void k_pool0(const float* __restrict__ src) {
    int img = blockIdx.x;
    int c0 = blockIdx.y * 32;
    float lox = 0.f, loy = 0.f;
    float bwx = 32.f / 7.f, bwy = 32.f / 7.f;
    __shared__ float sWx[224], sWy[224], tile[2][32 * 33];
    int tid = threadIdx.x;
    {
        int p = tid >> 5, i = tid & 31;
        float sx = lox + bwx * (float)p;
        sWx[tid] = hat_int(sx + bwx - (float)i) - hat_int(sx - (float)i);
        float sy = loy + bwy * (float)p;
        sWy[tid] = hat_int(sy + bwy - (float)i) - hat_int(sy - (float)i);
    }
    const float* Fp = src + (size_t)img * CCH * HWP + (size_t)c0 * HWP;
    for (int e = tid; e < 1024; e += 224) {
        int cc = e >> 5, w = e & 31;
        tile[0][cc * 33 + w] = Fp[(size_t)cc * HWP + w];
    }
    int c = tid & 31, q = tid >> 5;
    float acc[7] = {};
    for (int h = 0; h < 32; ++h) {
        __syncthreads();
        if (h < 31) {
            int hb = (h + 1) & 1;
            for (int e = tid; e < 1024; e += 224) {
                int cc = e >> 5, w = e & 31;
                tile[hb][cc * 33 + w] = Fp[(size_t)cc * HWP + (h + 1) * 32 + w];
            }
        }
        float t = 0.f;
        const float* wx = &sWx[q * 32];
        const float* tr = &tile[h & 1][c * 33];
        for (int w = 0; w < 32; ++w) t += tr[w] * wx[w];
#pragma unroll
        for (int p = 0; p < 7; ++p) acc[p] += t * sWy[p * 32 + h];
    }
    int d = c0 + c;
    float* o = g_I0 + ((size_t)img * CCH + d) * P2;
#pragma unroll
    for (int p = 0; p < 7; ++p) o[p * 7 + q] = acc[p];
}

// ---------------- K2b: ctx_pool --------------------------------------------------
__global__ void k_ctx(const float* __restrict__ Wc, const float* __restrict__ bc) {
    int b = blockIdx.x, pq = blockIdx.y;
    int c = threadIdx.x;
    __shared__ float S;
    if (c == 0) {
        int p = pq / 7, q = pq - p * 7;
        float bw = 32.f / 7.f;
        float sx = 0.f, sy = 0.f;
        float st = bw * q, en = st + bw;
        for (int i = 0; i < 32; ++i) sx += hat_int(en - (float)i) - hat_int(st - (float)i);
        st = bw * p; en = st + bw;
        for (int i = 0; i < 32; ++i) sy += hat_int(en - (float)i) - hat_int(st - (float)i);
        S = sx * sy;
    }
    __syncthreads();
    float acc = 0.f;
    const float* I = g_I0 + (size_t)b * CCH * P2 + pq;
    const float* w = Wc + c * CCH;
    for (int k = 0; k < CCH; ++k) acc += w[k] * I[k * P2];
    const float inv_area = (7.f * 7.f) / (32.f * 32.f);
    g_ctx[((size_t)b * CCH + c) * P2 + pq] = (acc + bc[c] * S) * inv_area;
}

// ---------------- K2c: K/L images, layout [img][s][pq][d] ----------------------
__global__ void k_KL(const float* __restrict__ Wof) {
    int b = blockIdx.x, s = blockIdx.y, pq = blockIdx.z;
    int d = threadIdx.x;
    float acc = 0.f;
    const float* w = Wof + d * 512 + 256 + s * 128;
    const float* x = g_ctx + ((size_t)b * CCH + s * 128) * P2 + pq;
    for (int k = 0; k < 128; ++k) acc += w[k] * x[k * P2];
    g_KL[((size_t)(b * 2 + s) * P2 + pq) * DD + d] = acc;
}

// ---------------- K6: A_sub/A_obj (fp16 out), layouts [roi][pq][d] -------------
__global__ void k_A(const float* __restrict__ Wrf) {
    int bi = blockIdx.x;
    int s = blockIdx.y;
    int d = threadIdx.x;
    __shared__ float Xs[64 * 49];   // [kl][pq]
    const float* X = g_objf + (size_t)bi * P2 * DD;   // [pq][k]
    const float* w = Wrf + d * 896 + s * 256;
    float acc[P2];
#pragma unroll
    for (int pq = 0; pq < P2; ++pq) acc[pq] = 0.f;
    for (int k0 = 0; k0 < 256; k0 += 64) {
        __syncthreads();
        for (int e = d; e < 64 * 49; e += 256) {
            int pq = e >> 6, kl = e & 63;
            Xs[kl * 49 + pq] = X[pq * 256 + k0 + kl];
        }
        __syncthreads();
        for (int kl = 0; kl < 64; ++kl) {
            float wv = w[k0 + kl];
            const float* xr = &Xs[kl * 49];
#pragma unroll
            for (int pq = 0; pq < P2; ++pq) acc[pq] += wv * xr[pq];
        }
    }
    __half* o = g_Ah + (((size_t)bi * 2 + s) * P2) * DD + d;
#pragma unroll
    for (int pq = 0; pq < P2; ++pq) o[(size_t)pq * DD] = __float2half(acc[pq]);
}

// ---------------- K7: pair assembly + relu, fp16 in/out, per unordered pair -----
__global__ void k_pair(const float* __restrict__ brf) {
    int bu = blockIdx.x;            // b*NU + u
    int b = bu / NU, u = bu - b * NU;
    int rem = u, i = 0;
    while (rem >= NO - i) { rem -= NO - i; ++i; }
    int j = i + rem;                // i <= j
    __shared__ float imA[P2], imB[P2];
    int tid = threadIdx.x;          // 256 = d
    if (tid < P2) {
        imA[tid] = g_imap[((size_t)bu * 2 + 0) * P2 + tid];
        imB[tid] = g_imap[((size_t)bu * 2 + 1) * P2 + tid];
    }
    __syncthreads();
    const __half* Ai_s = g_Ah + ((size_t)(b * NO + i) * 2 + 0) * P2 * DD;
    const __half* Ai_o = g_Ah + ((size_t)(b * NO + i) * 2 + 1) * P2 * DD;
    const __half* Aj_s = g_Ah + ((size_t)(b * NO + j) * 2 + 0) * P2 * DD;
    const __half* Aj_o = g_Ah + ((size_t)(b * NO + j) * 2 + 1) * P2 * DD;
    const __half* Pu = g_Puh + (size_t)bu * P2 * 768;
    __half* X0 = g_Xh + (size_t)(b * NPAIR + i * NO + j) * KFC;
    __half* X1 = g_Xh + (size_t)(b * NPAIR + j * NO + i) * KFC;
    float bv = brf[tid];
    bool diag = (i == j);
#pragma unroll 1
    for (int pq = 0; pq < P2; ++pq) {
        float ia = imA[pq], ib = imB[pq];
        const __half* pu = Pu + (size_t)pq * 768;
        float x = __half2float(pu[tid]);
        float y = __half2float(pu[256 + tid]);
        float z = __half2float(pu[512 + tid]);
        float ais = __half2float(Ai_s[(size_t)pq * DD + tid]);
        float ajo = __half2float(Aj_o[(size_t)pq * DD + tid]);
        float v0 = ais + ajo + x + ia * y + ib * z + bv;
        X0[pq * 256 + tid] = __float2half(fmaxf(v0, 0.f));
        if (!diag) {
            float ajs = __half2float(Aj_s[(size_t)pq * DD + tid]);
            float aio = __half2float(Ai_o[(size_t)pq * DD + tid]);
            float v1 = ajs + aio + x + ib * y + ia * z + bv;
            X1[pq * 256 + tid] = __float2half(fmaxf(v1, 0.f));
        }
    }
}

// ---------------- weight permutation: dst[n][pq*256+d] = W[n][d*49+pq] ----------
__global__ void k_permW(const float* __restrict__ W, float* __restrict__ dst) {
    __shared__ float s[64 * 49];
    int dg = blockIdx.x;
    int n = blockIdx.y;
    int tid = threadIdx.x;
    const float* src = W + (size_t)n * KFC + dg * 64 * 49;
    for (int e = tid; e < 64 * 49; e += 256) s[e] = src[e];
    __syncthreads();
    float* o = dst + (size_t)n * KFC + dg * 64;
    for (int e = tid; e < 64 * 49; e += 256) {
        int pq = e >> 6, dl = e & 63;
        o[(size_t)pq * 256 + dl] = s[dl * 49 + pq];
    }
}

// ---------------- rel FC: TF32 MMA, A read from fp16, split-K ------------------
__global__ __launch_bounds__(256) void k_fc_tf32(const float* __restrict__ W,
                                                 int M, int kchunk) {
    __shared__ unsigned As[16][136];
    __shared__ unsigned Bs[16][136];
    int m0 = blockIdx.x * 128, n0 = blockIdx.y * 128, z = blockIdx.z;
    int kb = z * kchunk;
    int tid = threadIdx.x;
    int row = tid >> 1, kq = (tid & 1) * 8;
    const __half* Ap = g_Xh + (size_t)(m0 + row) * KFC + kb + kq;
    const float* Bp = W + (size_t)(n0 + row) * KFC + kb + kq;
    int lane = tid & 31;
    int g = lane >> 2, tg = lane & 3;
    int warp = tid >> 5;
    int wm = (warp & 3) * 32, wn = (warp >> 2) * 64;

    float acc[2][8][4];
#pragma unroll
    for (int mi = 0; mi < 2; ++mi)
#pragma unroll
        for (int nj = 0; nj < 8; ++nj)
#pragma unroll
            for (int r = 0; r < 4; ++r) acc[mi][nj][r] = 0.f;

    uint4 rah = *(const uint4*)(Ap);          // 8 halves
    float4 rb0 = *(const float4*)(Bp);
    float4 rb1 = *(const float4*)(Bp + 4);

    for (int k0 = 0; k0 < kchunk; k0 += 16) {
        {
            __half2 h0 = *(__half2*)&rah.x, h1 = *(__half2*)&rah.y;
            __half2 h2 = *(__half2*)&rah.z, h3 = *(__half2*)&rah.w;
            float2 f0 = __half22float2(h0), f1 = __half22float2(h1);
            float2 f2 = __half22float2(h2), f3 = __half22float2(h3);
            As[kq + 0][row] = f2tf32(f0.x); As[kq + 1][row] = f2tf32(f0.y);
            As[kq + 2][row] = f2tf32(f1.x); As[kq + 3][row] = f2tf32(f1.y);
            As[kq + 4][row] = f2tf32(f2.x); As[kq + 5][row] = f2tf32(f2.y);
            As[kq + 6][row] = f2tf32(f3.x); As[kq + 7][row] = f2tf32(f3.y);
        }
        Bs[kq + 0][row] = f2tf32(rb0.x); Bs[kq + 1][row] = f2tf32(rb0.y);
        Bs[kq + 2][row] = f2tf32(rb0.z); Bs[kq + 3][row] = f2tf32(rb0.w);
        Bs[kq + 4][row] = f2tf32(rb1.x); Bs[kq + 5][row] = f2tf32(rb1.y);
        Bs[kq + 6][row] = f2tf32(rb1.z); Bs[kq + 7][row] = f2tf32(rb1.w);
        __syncthreads();
        int kn = k0 + 16;
        if (kn < kchunk) {
            rah = *(const uint4*)(Ap + kn);
            rb0 = *(const float4*)(Bp + kn);
            rb1 = *(const float4*)(Bp + kn + 4);
        }
#pragma unroll
        for (int kk = 0; kk < 16; kk += 8) {
            unsigned af[2][4];
#pragma unroll
            for (int mi = 0; mi < 2; ++mi) {
                int mb = wm + mi * 16;
                af[mi][0] = As[kk + tg][mb + g];
                af[mi][1] = As[kk + tg][mb + g + 8];
                af[mi][2] = As[kk + tg + 4][mb + g];
                af[mi][3] = As[kk + tg + 4][mb + g + 8];
            }
            unsigned bf[8][2];
#pragma unroll
            for (int nj = 0; nj < 8; ++nj) {
                bf[nj][0] = Bs[kk + tg][wn + nj * 8 + g];
                bf[nj][1] = Bs[kk + tg + 4][wn + nj * 8 + g];
            }
#pragma unroll
            for (int mi = 0; mi < 2; ++mi)
#pragma unroll
                for (int nj = 0; nj < 8; ++nj) {
                    asm volatile(
                        "mma.sync.aligned.m16n8k8.row.col.f32.tf32.tf32.f32 "
                        "{%0,%1,%2,%3},{%4,%5,%6,%7},{%8,%9},{%0,%1,%2,%3};"
                        : "+f"(acc[mi][nj][0]), "+f"(acc[mi][nj][1]),
                          "+f"(acc[mi][nj][2]), "+f"(acc[mi][nj][3])
                        : "r"(af[mi][0]), "r"(af[mi][1]), "r"(af[mi][2]), "r"(af[mi][3]),
                          "r"(bf[nj][0]), "r"(bf[nj][1]));
                }
        }
        __syncthreads();
    }
#pragma unroll
    for (int mi = 0; mi < 2; ++mi) {
        int m = m0 + wm + mi * 16 + g;
#pragma unroll
        for (int nj = 0; nj < 8; ++nj) {
            int n = n0 + wn + nj * 8 + 2 * tg;
            float* p0 = &g_part[((size_t)z * M + m) * 256 + n];
            float* p1 = &g_part[((size_t)z * M + m + 8) * 256 + n];
            *(float2*)p0 = make_float2(acc[mi][nj][0], acc[mi][nj][1]);
            *(float2*)p1 = make_float2(acc[mi][nj][2], acc[mi][nj][3]);
        }
    }
}

// ---------------- obj FC: fp32 SIMT, split-K, relu at load ----------------------
__global__ __launch_bounds__(256) void k_fc2(const float* __restrict__ W,
                                             int M, int kchunk) {
    __shared__ float As[16][128];
    __shared__ float Bs[16][128];
    const float* A = (const float*)g_objf;
    int m0 = blockIdx.x * 128, n0 = blockIdx.y * 128, z = blockIdx.z;
    int kb = z * kchunk;
    int tid = threadIdx.x;
    int tx = tid & 15, ty = tid >> 4;
    int arow = tid >> 1, akq = (tid & 1) * 8;
    const float* Ap = A + (size_t)(m0 + arow) * KFC + kb;
    const float* Bp = W + (size_t)(n0 + arow) * KFC + kb;
    float4 ra0 = *(const float4*)(Ap + akq);
    float4 ra1 = *(const float4*)(Ap + akq + 4);
    float4 rb0 = *(const float4*)(Bp + akq);
    float4 rb1 = *(const float4*)(Bp + akq + 4);
    float acc[8][8] = {};
    for (int k0 = 0; k0 < kchunk; k0 += 16) {
        ra0.x = fmaxf(ra0.x, 0.f); ra0.y = fmaxf(ra0.y, 0.f);
        ra0.z = fmaxf(ra0.z, 0.f); ra0.w = fmaxf(ra0.w, 0.f);
        ra1.x = fmaxf(ra1.x, 0.f); ra1.y = fmaxf(ra1.y, 0.f);
        ra1.z = fmaxf(ra1.z, 0.f); ra1.w = fmaxf(ra1.w, 0.f);
        As[akq + 0][arow] = ra0.x; As[akq + 1][arow] = ra0.y;
        As[akq + 2][arow] = ra0.z; As[akq + 3][arow] = ra0.w;
        As[akq + 4][arow] = ra1.x; As[akq + 5][arow] = ra1.y;
        As[akq + 6][arow] = ra1.z; As[akq + 7][arow] = ra1.w;
        Bs[akq + 0][arow] = rb0.x; Bs[akq + 1][arow] = rb0.y;
        Bs[akq + 2][arow] = rb0.z; Bs[akq + 3][arow] = rb0.w;
        Bs[akq + 4][arow] = rb1.x; Bs[akq + 5][arow] = rb1.y;
        Bs[akq + 6][arow] = rb1.z; Bs[akq + 7][arow] = rb1.w;
        __syncthreads();
        int kn = k0 + 16;
        if (kn < kchunk) {
            ra0 = *(const float4*)(Ap + kn + akq);
            ra1 = *(const float4*)(Ap + kn + akq + 4);
            rb0 = *(const float4*)(Bp + kn + akq);
            rb1 = *(const float4*)(Bp + kn + akq + 4);
        }
#pragma unroll
        for (int kk = 0; kk < 16; ++kk) {
            float4 a0 = *(const float4*)&As[kk][ty * 8];
            float4 a1 = *(const float4*)&As[kk][ty * 8 + 4];
            float4 b0 = *(const float4*)&Bs[kk][tx * 8];
            float4 b1 = *(const float4*)&Bs[kk][tx * 8 + 4];
            float av[8] = {a0.x, a0.y, a0.z, a0.w, a1.x, a1.y, a1.z, a1.w};
            float bv[8] = {b0.x, b0.y, b0.z, b0.w, b1.x, b1.y, b1.z, b1.w};
#pragma unroll
            for (int i = 0; i < 8; ++i)
#pragma unroll
                for (int j = 0; j < 8; ++j) acc[i][j] += av[i] * bv[j];
        }
        __syncthreads();
    }
#pragma unroll
    for (int i = 0; i < 8; ++i) {
        int m = m0 + ty * 8 + i;
        float* o = &g_part[((size_t)z * M + m) * 256 + n0 + tx * 8];
        *(float4*)o       = make_float4(acc[i][0], acc[i][1], acc[i][2], acc[i][3]);
        *(float4*)(o + 4) = make_float4(acc[i][4], acc[i][5], acc[i][6], acc[i][7]);
    }
}

// reduce split-K partials + bias
__global__ void k_reduce(int which, const float* __restrict__ bias, int M, int Z) {
    int idx = blockIdx.x * 256 + threadIdx.x;
    if (idx >= M * 256) return;
    float s = bias[idx & 255];
    for (int z = 0; z < Z; ++z) s += g_part[(size_t)z * M * 256 + idx];
    if (which) g_O[idx] = s; else g_R[idx] = s;
}

// ---------------- K10: L2 normalize ---------------------------------------------
__global__ void k_norm(float* __restrict__ dst, int which) {
    int r = blockIdx.x, tid = threadIdx.x;
    const float* src = which ? (const float*)g_R : (const float*)g_O;
    float v = src[(size_t)r * DD + tid];
    float s = v * v;
#pragma unroll
    for (int o = 16; o > 0; o >>= 1) s += __shfl_xor_sync(0xffffffffu, s, o);
    __shared__ float ws[8];
    if ((tid & 31) == 0) ws[tid >> 5] = s;
    __syncthreads();
    float tot = 0.f;
#pragma unroll
    for (int k = 0; k < 8; ++k) tot += ws[k];
    dst[(size_t)r * DD + tid] = v * rsqrtf(tot);
}

// ---------------- launch ----------------------------------------------------------
extern "C" void kernel_launch(void* const* d_in, const int* in_sizes, int n_in,
                              void* d_out, int out_size) {
    const float* input   = (const float*)d_in[0];
    const float* objects = (const float*)d_in[1];
    const float* Wc   = (const float*)d_in[3];
    const float* bc   = (const float*)d_in[4];
    const float* Wr   = (const float*)d_in[5];
    const float* br   = (const float*)d_in[6];
    const float* Wof  = (const float*)d_in[7];
    const float* bof  = (const float*)d_in[8];
    const float* Wrf  = (const float*)d_in[9];
    const float* brf  = (const float*)d_in[10];
    const float* Wofc = (const float*)d_in[11];
    const float* bofc = (const float*)d_in[12];
    const float* Wrfc = (const float*)d_in[13];
    const float* brfc = (const float*)d_in[14];
    float* out = (float*)d_out;

    float* wp;  cudaGetSymbolAddress((void**)&wp,  g_Wp);
    float* wp2; cudaGetSymbolAddress((void**)&wp2, g_Wp2);

    k_combine<<<1025, 256>>>(Wof, Wrf, Wr, br, objects);                 // +rank block
    k_projT<<<dim3(8, 8, 8), 256>>>(input);
    k_geom<<<8, 256>>>(objects);
    k_poolT<<<dim3(1088, 3), 256>>>(nullptr, 2, NU, nullptr);            // union pool (profiled, area-sorted)
    k_pool0<<<dim3(8, 8), 224>>>(input);                                 // I0 raw
    k_ctx<<<dim3(8, 49), 256>>>(Wc, bc);
    k_KL<<<dim3(8, 2, 49), 256>>>(Wof);
    k_poolT<<<dim3(128, 1), 256>>>(objects, 1, NO, bof);                 // obj pool + epi
    k_A<<<dim3(128, 2), 256>>>(Wrf);
    k_pair<<<1088, 256>>>(brf);
    k_permW<<<dim3(4, 256), 256>>>(Wrfc, wp);
    k_fc_tf32<<<dim3(16, 2, 8), 256>>>(wp, 2048, 1568);                  // rel FC (TF32, fp16 A)
    k_reduce<<<2048, 256>>>(0, brfc, 2048, 8);
    k_permW<<<dim3(4, 256), 256>>>(Wofc, wp2);
    k_fc2<<<dim3(1, 2, 16), 256>>>(wp2, 128, 784);                       // obj FC
    k_reduce<<<128, 256>>>(1, bofc, 128, 16);
    k_norm<<<128, 256>>>(out, 0);                                        // obj_out
    k_norm<<<2048, 256>>>(out + 32768, 1);                               // rel_out
    (void)in_sizes; (void)n_in; (void)out_size;
}

// round 14
// speedup vs baseline: 1.0833x; 1.0833x over previous
#include <cuda_runtime.h>
#include <cuda_fp16.h>

// ---------------- problem constants ----------------
#define BB    8
#define CCH   256
#define HWP   1024
#define NO    16
#define NPAIR 256
#define NU    136
#define P2    49
#define DD    256
#define KFC   12544
#define FCH   1024

typedef unsigned long long u64;

// ---------------- scratch ----------------
__device__ float g_M[FCH * CCH];
__device__ float g_cb[FCH];
__device__ float g_Ft[BB * HWP * FCH];                 // channel-last projected features
__device__ float g_I0[BB * CCH * P2];
__device__ float g_ctx[BB * CCH * P2];
__device__ float g_KL[BB * 2 * P2 * DD];               // [img][s][pq][d]
__device__ float g_ub[BB * NU * 4];
__device__ float g_imap[BB * NU * 2 * P2];
__device__ float g_bimap[BB * NO * P2];
__device__ float g_objf[BB * NO * P2 * DD];            // [roi][pq][d]
__device__ __half g_Ah[BB * NO * 2 * P2 * DD];         // A_sub/A_obj, fp16
__device__ __half g_Puh[BB * NU * P2 * 768];           // pooled rel, fp16
__device__ __half g_Xh[(size_t)BB * NPAIR * KFC];      // relu(rel_feat), fp16
__device__ __half g_Wph[DD * KFC];                     // Wrfc permuted, fp16
__device__ float g_Wp2[DD * KFC];                      // Wofc permuted, fp32
__device__ float g_part[8 * 2048 * 256];
__device__ float g_R[BB * NPAIR * DD];
__device__ float g_O[BB * NO * DD];

__device__ __forceinline__ float hat_int(float t) {
    t = fminf(1.f, fmaxf(-1.f, t));
    return (t < 0.f) ? 0.5f * (t + 1.f) * (t + 1.f) : 1.f - 0.5f * (1.f - t) * (1.f - t);
}

__device__ __forceinline__ unsigned f2tf32(float x) {
    unsigned r;
    asm("cvt.rna.tf32.f32 %0, %1;" : "=r"(r) : "f"(x));
    return r;
}

// ---- packed f32x2 helpers ----
__device__ __forceinline__ u64 pk2(float lo, float hi) {
    u64 r;
    asm("mov.b64 %0, {%1, %2};" : "=l"(r) : "f"(lo), "f"(hi));
    return r;
}
__device__ __forceinline__ u64 fma2(u64 a, u64 b, u64 c) {
    u64 d;
    asm("fma.rn.f32x2 %0, %1, %2, %3;" : "=l"(d) : "l"(a), "l"(b), "l"(c));
    return d;
}
__device__ __forceinline__ void upk2(u64 v, float& lo, float& hi) {
    asm("mov.b64 {%0, %1}, %2;" : "=f"(lo), "=f"(hi) : "l"(v));
}

// ---------------- K0: combine weights ------------------------------------------
__global__ void k_combine(const float* __restrict__ Wof, const float* __restrict__ Wrf,
                          const float* __restrict__ Wr, const float* __restrict__ br) {
    int row = blockIdx.x;
    int c = threadIdx.x;
    if (row < 256) {
        g_M[row * CCH + c] = Wof[row * 512 + c];
        if (c == 0) g_cb[row] = 0.f;
    } else {
        int s = (row - 256) >> 8;
        int d = (row - 256) & 255;
        const float* w = Wrf + d * 896 + 512 + s * 128;
        float acc = 0.f;
        for (int k = 0; k < 128; ++k) acc += w[k] * Wr[(s * 128 + k) * CCH + c];
        g_M[row * CCH + c] = acc;
        if (c == 0) {
            float cb = 0.f;
            for (int k = 0; k < 128; ++k) cb += w[k] * br[s * 128 + k];
            g_cb[row] = cb;
        }
    }
}

// ---------------- K1: projection GEMM (transposed output), FFMA2 ---------------
__global__ __launch_bounds__(256) void k_projT(const float* __restrict__ input) {
    __shared__ float As[16][128];   // [k][n]
    __shared__ float Bs[16][128];   // [k][m]
    int b = blockIdx.z;
    const float* In = input + (size_t)b * CCH * HWP;
    float* C = g_Ft + (size_t)b * HWP * FCH;
    int m0 = blockIdx.x * 128, n0 = blockIdx.y * 128;
    int tid = threadIdx.x;
    int tx = tid & 15, ty = tid >> 4;
    int krow = tid >> 4, ncol = (tid & 15) * 8;
    int mrow = tid >> 1, kq = (tid & 1) * 8;
    const float* Apt = In + n0 + ncol;
    const float* Bpt = g_M + (size_t)(m0 + mrow) * CCH;
    float4 ra0 = *(const float4*)(Apt + (size_t)krow * HWP);
    float4 ra1 = *(const float4*)(Apt + (size_t)krow * HWP + 4);
    float4 rb0 = *(const float4*)(Bpt + kq);
    float4 rb1 = *(const float4*)(Bpt + kq + 4);
    u64 accp[8][4];
#pragma unroll
    for (int i = 0; i < 8; ++i)
#pragma unroll
        for (int jp = 0; jp < 4; ++jp) accp[i][jp] = 0ull;
    for (int k0 = 0; k0 < CCH; k0 += 16) {
        *(float4*)&As[krow][ncol] = ra0;
        *(float4*)&As[krow][ncol + 4] = ra1;
        Bs[kq + 0][mrow] = rb0.x; Bs[kq + 1][mrow] = rb0.y;
        Bs[kq + 2][mrow] = rb0.z; Bs[kq + 3][mrow] = rb0.w;
        Bs[kq + 4][mrow] = rb1.x; Bs[kq + 5][mrow] = rb1.y;
        Bs[kq + 6][mrow] = rb1.z; Bs[kq + 7][mrow] = rb1.w;
        __syncthreads();
        int kn = k0 + 16;
        if (kn < CCH) {
            ra0 = *(const float4*)(Apt + (size_t)(kn + krow) * HWP);
            ra1 = *(const float4*)(Apt + (size_t)(kn + krow) * HWP + 4);
            rb0 = *(const float4*)(Bpt + kn + kq);
            rb1 = *(const float4*)(Bpt + kn + kq + 4);
        }
#pragma unroll
        for (int kk = 0; kk < 16; ++kk) {
            float4 a0 = *(const float4*)&As[kk][ty * 8];
            float4 a1 = *(const float4*)&As[kk][ty * 8 + 4];
            ulonglong2 bv0 = *(const ulonglong2*)&Bs[kk][tx * 8];
            ulonglong2 bv1 = *(const ulonglong2*)&Bs[kk][tx * 8 + 4];
            u64 bp[4] = {bv0.x, bv0.y, bv1.x, bv1.y};
            float av[8] = {a0.x, a0.y, a0.z, a0.w, a1.x, a1.y, a1.z, a1.w};
#pragma unroll
            for (int i = 0; i < 8; ++i) {
                u64 ap = pk2(av[i], av[i]);
#pragma unroll
                for (int jp = 0; jp < 4; ++jp)
                    accp[i][jp] = fma2(ap, bp[jp], accp[i][jp]);
            }
        }
        __syncthreads();
    }
    float4 cb0 = *(const float4*)&g_cb[m0 + tx * 8];
    float4 cb1 = *(const float4*)&g_cb[m0 + tx * 8 + 4];
    float cb[8] = {cb0.x, cb0.y, cb0.z, cb0.w, cb1.x, cb1.y, cb1.z, cb1.w};
#pragma unroll
    for (int i = 0; i < 8; ++i) {
        int n = n0 + ty * 8 + i;
        float o[8];
#pragma unroll
        for (int jp = 0; jp < 4; ++jp) upk2(accp[i][jp], o[2 * jp], o[2 * jp + 1]);
#pragma unroll
        for (int j = 0; j < 8; ++j) o[j] += cb[j];
        *(float4*)&C[(size_t)n * FCH + m0 + tx * 8]     = make_float4(o[0], o[1], o[2], o[3]);
        *(float4*)&C[(size_t)n * FCH + m0 + tx * 8 + 4] = make_float4(o[4], o[5], o[6], o[7]);
    }
}

// ---------------- K3: geometry ---------------------------------------------------
__global__ void k_geom(const float* __restrict__ objects) {
    int b = blockIdx.x;
    int tid = threadIdx.x;
    const float* obj = objects + b * NO * 4;
    __shared__ float sub[NU * 4];
    if (tid < NU) {
        int rem = tid, i = 0;
        while (rem >= NO - i) { rem -= NO - i; ++i; }
        int j = i + rem;
        float x0 = fminf(obj[i * 4 + 0], obj[j * 4 + 0]);
        float y0 = fminf(obj[i * 4 + 1], obj[j * 4 + 1]);
        float x1 = fmaxf(obj[i * 4 + 2], obj[j * 4 + 2]);
        float y1 = fmaxf(obj[i * 4 + 3], obj[j * 4 + 3]);
        sub[tid * 4 + 0] = x0; sub[tid * 4 + 1] = y0; sub[tid * 4 + 2] = x1; sub[tid * 4 + 3] = y1;
        float* gu = g_ub + (b * NU + tid) * 4;
        gu[0] = x0; gu[1] = y0; gu[2] = x1; gu[3] = y1;
    }
    __syncthreads();
    int total = (NO + NU * 2) * P2;
    for (int v = tid; v < total; v += blockDim.x) {
        int m = v / P2, pq = v - (v / P2) * P2;
        int p = pq / 7, q = pq - p * 7;
        float b1x0, b1y0, b1x1, b1y1, g0x, g0y, g1x, g1y;
        float* dst;
        if (m < NO) {
            b1x0 = obj[m * 4 + 0]; b1y0 = obj[m * 4 + 1]; b1x1 = obj[m * 4 + 2]; b1y1 = obj[m * 4 + 3];
            g0x = 0.f; g0y = 0.f; g1x = 512.f; g1y = 512.f;
            dst = &g_bimap[(b * NO + m) * P2 + pq];
        } else {
            int mm = m - NO;
            int u = mm >> 1, ab = mm & 1;
            int rem = u, i = 0;
            while (rem >= NO - i) { rem -= NO - i; ++i; }
            int j = i + rem;
            int ob = ab ? j : i;
            b1x0 = obj[ob * 4 + 0]; b1y0 = obj[ob * 4 + 1]; b1x1 = obj[ob * 4 + 2]; b1y1 = obj[ob * 4 + 3];
            g0x = sub[u * 4 + 0]; g0y = sub[u * 4 + 1]; g1x = sub[u * 4 + 2]; g1y = sub[u * 4 + 3];
            dst = &g_imap[((b * NU + u) * 2 + ab) * P2 + pq];
        }
        float bw = (g1x - g0x) * (1.f / 7.f), bh = (g1y - g0y) * (1.f / 7.f);
        float gx0 = g0x + bw * (float)q, gy0 = g0y + bh * (float)p;
        float ox = fmaxf(0.f, fminf(gx0 + bw, b1x1) - fmaxf(gx0, b1x0));
        float oy = fmaxf(0.f, fminf(gy0 + bh, b1y1) - fmaxf(gy0, b1y0));
        *dst = oy * ox / fmaxf(bw * bh, 1e-8f);
    }
}

// ---------------- channel-last pooling, FFMA2 (R12 form) -----------------------
__global__ __launch_bounds__(256, 3) void k_poolT(const float* __restrict__ boxes,
                                                  int mode, int rois_per_img,
                                                  const float* __restrict__ bof) {
    int roi = blockIdx.x;
    int cg = blockIdx.y;
    int img = roi / rois_per_img;
    const float* bp = (mode == 1) ? (boxes + roi * 4) : (g_ub + roi * 4);
    float bx0 = bp[0], by0 = bp[1], bx1 = bp[2], by1 = bp[3];
    const float s16 = 0.0625f;
    float lox = bx0 * s16, hix = bx1 * s16, loy = by0 * s16, hiy = by1 * s16;
    float bwx = (hix - lox) * (1.f / 7.f), bwy = (hiy - loy) * (1.f / 7.f);
    float inv_area = 1.f / fmaxf(bwx * bwy, 1e-8f);

    __shared__ float wx7[32][8];
    __shared__ float wy7[32][8];
    int tid = threadIdx.x;
    if (tid < 64) {
        int w = tid & 31;
        bool isy = tid >= 32;
        float lo = isy ? loy : lox;
        float bwv = isy ? bwy : bwx;
        float* dst = isy ? &wy7[w][0] : &wx7[w][0];
#pragma unroll
        for (int q = 0; q < 7; ++q) {
            float s = lo + bwv * (float)q;
            dst[q] = hat_int(s + bwv - (float)w) - hat_int(s - (float)w);
        }
        dst[7] = 0.f;
    }
    __syncthreads();

    int hmin = max(0, (int)ceilf(loy - 1.f));
    int hmax = min(31, (int)floorf(hiy + 1.f));
    int wmin = max(0, (int)ceilf(lox - 1.f));
    int wmax = min(31, (int)floorf(hix + 1.f));

    int ch_off = (mode == 2) ? (256 + cg * 256) : 0;
    const float* Fp = g_Ft + (size_t)img * HWP * FCH + ch_off + tid;

    u64 acc2[7][4];
#pragma unroll
    for (int p = 0; p < 7; ++p)
#pragma unroll
        for (int k = 0; k < 4; ++k) acc2[p][k] = 0ull;

    for (int h = hmin; h <= hmax; ++h) {
        u64 tq2[4] = {0ull, 0ull, 0ull, 0ull};
        const float* Fh = Fp + (size_t)(h * 32) * FCH;
        for (int w = wmin; w <= wmax; ++w) {
            float f = Fh[(size_t)w * FCH];
            u64 ff = pk2(f, f);
            ulonglong2 wa = *(const ulonglong2*)&wx7[w][0];
            ulonglong2 wb = *(const ulonglong2*)&wx7[w][4];
            tq2[0] = fma2(ff, wa.x, tq2[0]);
            tq2[1] = fma2(ff, wa.y, tq2[1]);
            tq2[2] = fma2(ff, wb.x, tq2[2]);
            tq2[3] = fma2(ff, wb.y, tq2[3]);
        }
#pragma unroll
        for (int p = 0; p < 7; ++p) {
            float wyv = wy7[h][p];
            u64 wyp = pk2(wyv, wyv);
#pragma unroll
            for (int k = 0; k < 4; ++k) acc2[p][k] = fma2(wyp, tq2[k], acc2[p][k]);
        }
    }

    if (mode == 2) {
        __half* o = g_Puh + (size_t)roi * P2 * 768 + cg * 256 + tid;
#pragma unroll
        for (int p = 0; p < 7; ++p) {
            float aq[8];
#pragma unroll
            for (int k = 0; k < 4; ++k) upk2(acc2[p][k], aq[2 * k], aq[2 * k + 1]);
#pragma unroll
            for (int q = 0; q < 7; ++q)
                o[(size_t)(p * 7 + q) * 768] = __float2half(aq[q] * inv_area);
        }
    } else {
        const float* K = g_KL + ((size_t)(img * 2 + 0) * P2) * DD + tid;
        const float* L = g_KL + ((size_t)(img * 2 + 1) * P2) * DD + tid;
        const float* bm = g_bimap + (size_t)roi * P2;
        float bv = bof[tid];
        float* o = g_objf + (size_t)roi * P2 * DD + tid;
#pragma unroll
        for (int p = 0; p < 7; ++p) {
            float aq[8];
#pragma unroll
            for (int k = 0; k < 4; ++k) upk2(acc2[p][k], aq[2 * k], aq[2 * k + 1]);
#pragma unroll
            for (int q = 0; q < 7; ++q) {
                int pq = p * 7 + q;
                o[(size_t)pq * DD] = aq[q] * inv_area + K[(size_t)pq * DD]
                                   + L[(size_t)pq * DD] * bm[pq] + bv;
            }
        }
    }
}

// ---------------- mode-0 pool: raw input full-image box -> g_I0 ----------------
__global__ void k_pool0(const float* __restrict__ src) {
    int img = blockIdx.x;
    int c0 = blockIdx.y * 32;
    float lox = 0.f, loy = 0.f;
    float bwx = 32.f / 7.f, bwy = 32.f / 7.f;
    __shared__ float sWx[224], sWy[224], tile[2][32 * 33];
    int tid = threadIdx.x;
    {
        int p = tid >> 5, i = tid & 31;
        float sx = lox + bwx * (float)p;
        sWx[tid] = hat_int(sx + bwx - (float)i) - hat_int(sx - (float)i);
        float sy = loy + bwy * (float)p;
        sWy[tid] = hat_int(sy + bwy - (float)i) - hat_int(sy - (float)i);
    }
    const float* Fp = src + (size_t)img * CCH * HWP + (size_t)c0 * HWP;
    for (int e = tid; e < 1024; e += 224) {
        int cc = e >> 5, w = e & 31;
        tile[0][cc * 33 + w] = Fp[(size_t)cc * HWP + w];
    }
    int c = tid & 31, q = tid >> 5;
    float acc[7] = {};
    for (int h = 0; h < 32; ++h) {
        __syncthreads();
        if (h < 31) {
            int hb = (h + 1) & 1;
            for (int e = tid; e < 1024; e += 224) {
                int cc = e >> 5, w = e & 31;
                tile[hb][cc * 33 + w] = Fp[(size_t)cc * HWP + (h + 1) * 32 + w];
            }
        }
        float t = 0.f;
        const float* wx = &sWx[q * 32];
        const float* tr = &tile[h & 1][c * 33];
        for (int w = 0; w < 32; ++w) t += tr[w] * wx[w];
#pragma unroll
        for (int p = 0; p < 7; ++p) acc[p] += t * sWy[p * 32 + h];
    }
    int d = c0 + c;
    float* o = g_I0 + ((size_t)img * CCH + d) * P2;
#pragma unroll
    for (int p = 0; p < 7; ++p) o[p * 7 + q] = acc[p];
}

// ---------------- K2b: ctx_pool --------------------------------------------------
__global__ void k_ctx(const float* __restrict__ Wc, const float* __restrict__ bc) {
    int b = blockIdx.x, pq = blockIdx.y;
    int c = threadIdx.x;
    __shared__ float S;
    if (c == 0) {
        int p = pq / 7, q = pq - p * 7;
        float bw = 32.f / 7.f;
        float sx = 0.f, sy = 0.f;
        float st = bw * q, en = st + bw;
        for (int i = 0; i < 32; ++i) sx += hat_int(en - (float)i) - hat_int(st - (float)i);
        st = bw * p; en = st + bw;
        for (int i = 0; i < 32; ++i) sy += hat_int(en - (float)i) - hat_int(st - (float)i);
        S = sx * sy;
    }
    __syncthreads();
    float acc = 0.f;
    const float* I = g_I0 + (size_t)b * CCH * P2 + pq;
    const float* w = Wc + c * CCH;
    for (int k = 0; k < CCH; ++k) acc += w[k] * I[k * P2];
    const float inv_area = (7.f * 7.f) / (32.f * 32.f);
    g_ctx[((size_t)b * CCH + c) * P2 + pq] = (acc + bc[c] * S) * inv_area;
}

// ---------------- K2c: K/L images, layout [img][s][pq][d] ----------------------
__global__ void k_KL(const float* __restrict__ Wof) {
    int b = blockIdx.x, s = blockIdx.y, pq = blockIdx.z;
    int d = threadIdx.x;
    float acc = 0.f;
    const float* w = Wof + d * 512 + 256 + s * 128;
    const float* x = g_ctx + ((size_t)b * CCH + s * 128) * P2 + pq;
    for (int k = 0; k < 128; ++k) acc += w[k] * x[k * P2];
    g_KL[((size_t)(b * 2 + s) * P2 + pq) * DD + d] = acc;
}

// ---------------- K6: A_sub/A_obj (fp16 out), layouts [roi][pq][d] -------------
__global__ void k_A(const float* __restrict__ Wrf) {
    int bi = blockIdx.x;
    int s = blockIdx.y;
    int d = threadIdx.x;
    __shared__ float Xs[64 * 49];   // [kl][pq]
    const float* X = g_objf + (size_t)bi * P2 * DD;   // [pq][k]
    const float* w = Wrf + d * 896 + s * 256;
    float acc[P2];
#pragma unroll
    for (int pq = 0; pq < P2; ++pq) acc[pq] = 0.f;
    for (int k0 = 0; k0 < 256; k0 += 64) {
        __syncthreads();
        for (int e = d; e < 64 * 49; e += 256) {
            int pq = e >> 6, kl = e & 63;
            Xs[kl * 49 + pq] = X[pq * 256 + k0 + kl];
        }
        __syncthreads();
        for (int kl = 0; kl < 64; ++kl) {
            float wv = w[k0 + kl];
            const float* xr = &Xs[kl * 49];
#pragma unroll
            for (int pq = 0; pq < P2; ++pq) acc[pq] += wv * xr[pq];
        }
    }
    __half* o = g_Ah + (((size_t)bi * 2 + s) * P2) * DD + d;
#pragma unroll
    for (int pq = 0; pq < P2; ++pq) o[(size_t)pq * DD] = __float2half(acc[pq]);
}

// ---------------- K7: pair assembly + relu, fp16 in/out, per unordered pair -----
__global__ void k_pair(const float* __restrict__ brf) {
    int bu = blockIdx.x;            // b*NU + u
    int b = bu / NU, u = bu - b * NU;
    int rem = u, i = 0;
    while (rem >= NO - i) { rem -= NO - i; ++i; }
    int j = i + rem;                // i <= j
    __shared__ float imA[P2], imB[P2];
    int tid = threadIdx.x;          // 256 = d
    if (tid < P2) {
        imA[tid] = g_imap[((size_t)bu * 2 + 0) * P2 + tid];
        imB[tid] = g_imap[((size_t)bu * 2 + 1) * P2 + tid];
    }
    __syncthreads();
    const __half* Ai_s = g_Ah + ((size_t)(b * NO + i) * 2 + 0) * P2 * DD;
    const __half* Ai_o = g_Ah + ((size_t)(b * NO + i) * 2 + 1) * P2 * DD;
    const __half* Aj_s = g_Ah + ((size_t)(b * NO + j) * 2 + 0) * P2 * DD;
    const __half* Aj_o = g_Ah + ((size_t)(b * NO + j) * 2 + 1) * P2 * DD;
    const __half* Pu = g_Puh + (size_t)bu * P2 * 768;
    __half* X0 = g_Xh + (size_t)(b * NPAIR + i * NO + j) * KFC;
    __half* X1 = g_Xh + (size_t)(b * NPAIR + j * NO + i) * KFC;
    float bv = brf[tid];
    bool diag = (i == j);
#pragma unroll 1
    for (int pq = 0; pq < P2; ++pq) {
        float ia = imA[pq], ib = imB[pq];
        const __half* pu = Pu + (size_t)pq * 768;
        float x = __half2float(pu[tid]);
        float y = __half2float(pu[256 + tid]);
        float z = __half2float(pu[512 + tid]);
        float ais = __half2float(Ai_s[(size_t)pq * DD + tid]);
        float ajo = __half2float(Aj_o[(size_t)pq * DD + tid]);
        float v0 = ais + ajo + x + ia * y + ib * z + bv;
        X0[pq * 256 + tid] = __float2half(fmaxf(v0, 0.f));
        if (!diag) {
            float ajs = __half2float(Aj_s[(size_t)pq * DD + tid]);
            float aio = __half2float(Ai_o[(size_t)pq * DD + tid]);
            float v1 = ajs + aio + x + ib * y + ia * z + bv;
            X1[pq * 256 + tid] = __float2half(fmaxf(v1, 0.f));
        }
    }
}

// ---------------- weight permutations --------------------------------------------
// rel: dst (fp16) [n][pq*256+d] = W[n][d*49+pq]
__global__ void k_permWh(const float* __restrict__ W, __half* __restrict__ dst) {
    __shared__ float s[64 * 49];
    int dg = blockIdx.x;
    int n = blockIdx.y;
    int tid = threadIdx.x;
    const float* src = W + (size_t)n * KFC + dg * 64 * 49;
    for (int e = tid; e < 64 * 49; e += 256) s[e] = src[e];
    __syncthreads();
    __half* o = dst + (size_t)n * KFC + dg * 64;
    for (int e = tid; e < 64 * 49; e += 256) {
        int pq = e >> 6, dl = e & 63;
        o[(size_t)pq * 256 + dl] = __float2half(s[dl * 49 + pq]);
    }
}
// obj: dst (fp32)
__global__ void k_permW(const float* __restrict__ W, float* __restrict__ dst) {
    __shared__ float s[64 * 49];
    int dg = blockIdx.x;
    int n = blockIdx.y;
    int tid = threadIdx.x;
    const float* src = W + (size_t)n * KFC + dg * 64 * 49;
    for (int e = tid; e < 64 * 49; e += 256) s[e] = src[e];
    __syncthreads();
    float* o = dst + (size_t)n * KFC + dg * 64;
    for (int e = tid; e < 64 * 49; e += 256) {
        int pq = e >> 6, dl = e & 63;
        o[(size_t)pq * 256 + dl] = s[dl * 49 + pq];
    }
}

// ---------------- rel FC: TF32 MMA, A and B read from fp16, split-K ------------
__global__ __launch_bounds__(256) void k_fc_tf32(int M, int kchunk) {
    __shared__ unsigned As[16][136];
    __shared__ unsigned Bs[16][136];
    int m0 = blockIdx.x * 128, n0 = blockIdx.y * 128, z = blockIdx.z;
    int kb = z * kchunk;
    int tid = threadIdx.x;
    int row = tid >> 1, kq = (tid & 1) * 8;
    const __half* Ap = g_Xh + (size_t)(m0 + row) * KFC + kb + kq;
    const __half* Bp = g_Wph + (size_t)(n0 + row) * KFC + kb + kq;
    int lane = tid & 31;
    int g = lane >> 2, tg = lane & 3;
    int warp = tid >> 5;
    int wm = (warp & 3) * 32, wn = (warp >> 2) * 64;

    float acc[2][8][4];
#pragma unroll
    for (int mi = 0; mi < 2; ++mi)
#pragma unroll
        for (int nj = 0; nj < 8; ++nj)
#pragma unroll
            for (int r = 0; r < 4; ++r) acc[mi][nj][r] = 0.f;

    uint4 rah = *(const uint4*)(Ap);
    uint4 rbh = *(const uint4*)(Bp);

    for (int k0 = 0; k0 < kchunk; k0 += 16) {
        {
            float2 f0 = __half22float2(*(__half2*)&rah.x), f1 = __half22float2(*(__half2*)&rah.y);
            float2 f2 = __half22float2(*(__half2*)&rah.z), f3 = __half22float2(*(__half2*)&rah.w);
            As[kq + 0][row] = f2tf32(f0.x); As[kq + 1][row] = f2tf32(f0.y);
            As[kq + 2][row] = f2tf32(f1.x); As[kq + 3][row] = f2tf32(f1.y);
            As[kq + 4][row] = f2tf32(f2.x); As[kq + 5][row] = f2tf32(f2.y);
            As[kq + 6][row] = f2tf32(f3.x); As[kq + 7][row] = f2tf32(f3.y);
        }
        {
            float2 f0 = __half22float2(*(__half2*)&rbh.x), f1 = __half22float2(*(__half2*)&rbh.y);
            float2 f2 = __half22float2(*(__half2*)&rbh.z), f3 = __half22float2(*(__half2*)&rbh.w);
            Bs[kq + 0][row] = f2tf32(f0.x); Bs[kq + 1][row] = f2tf32(f0.y);
            Bs[kq + 2][row] = f2tf32(f1.x); Bs[kq + 3][row] = f2tf32(f1.y);
            Bs[kq + 4][row] = f2tf32(f2.x); Bs[kq + 5][row] = f2tf32(f2.y);
            Bs[kq + 6][row] = f2tf32(f3.x); Bs[kq + 7][row] = f2tf32(f3.y);
        }
        __syncthreads();
        int kn = k0 + 16;
        if (kn < kchunk) {
            rah = *(const uint4*)(Ap + kn);
            rbh = *(const uint4*)(Bp + kn);
        }
#pragma unroll
        for (int kk = 0; kk < 16; kk += 8) {
            unsigned af[2][4];
#pragma unroll
            for (int mi = 0; mi < 2; ++mi) {
                int mb = wm + mi * 16;
                af[mi][0] = As[kk + tg][mb + g];
                af[mi][1] = As[kk + tg][mb + g + 8];
                af[mi][2] = As[kk + tg + 4][mb + g];
                af[mi][3] = As[kk + tg + 4][mb + g + 8];
            }
            unsigned bf[8][2];
#pragma unroll
            for (int nj = 0; nj < 8; ++nj) {
                bf[nj][0] = Bs[kk + tg][wn + nj * 8 + g];
                bf[nj][1] = Bs[kk + tg + 4][wn + nj * 8 + g];
            }
#pragma unroll
            for (int mi = 0; mi < 2; ++mi)
#pragma unroll
                for (int nj = 0; nj < 8; ++nj) {
                    asm volatile(
                        "mma.sync.aligned.m16n8k8.row.col.f32.tf32.tf32.f32 "
                        "{%0,%1,%2,%3},{%4,%5,%6,%7},{%8,%9},{%0,%1,%2,%3};"
                        : "+f"(acc[mi][nj][0]), "+f"(acc[mi][nj][1]),
                          "+f"(acc[mi][nj][2]), "+f"(acc[mi][nj][3])
                        : "r"(af[mi][0]), "r"(af[mi][1]), "r"(af[mi][2]), "r"(af[mi][3]),
                          "r"(bf[nj][0]), "r"(bf[nj][1]));
                }
        }
        __syncthreads();
    }
#pragma unroll
    for (int mi = 0; mi < 2; ++mi) {
        int m = m0 + wm + mi * 16 + g;
#pragma unroll
        for (int nj = 0; nj < 8; ++nj) {
            int n = n0 + wn + nj * 8 + 2 * tg;
            float* p0 = &g_part[((size_t)z * M + m) * 256 + n];
            float* p1 = &g_part[((size_t)z * M + m + 8) * 256 + n];
            *(float2*)p0 = make_float2(acc[mi][nj][0], acc[mi][nj][1]);
            *(float2*)p1 = make_float2(acc[mi][nj][2], acc[mi][nj][3]);
        }
    }
}

// ---------------- obj FC: fp32 SIMT, split-K, relu at load ----------------------
__global__ __launch_bounds__(256) void k_fc2(const float* __restrict__ W,
                                             int M, int kchunk) {
    __shared__ float As[16][128];
    __shared__ float Bs[16][128];
    const float* A = (const float*)g_objf;
    int m0 = blockIdx.x * 128, n0 = blockIdx.y * 128, z = blockIdx.z;
    int kb = z * kchunk;
    int tid = threadIdx.x;
    int tx = tid & 15, ty = tid >> 4;
    int arow = tid >> 1, akq = (tid & 1) * 8;
    const float* Ap = A + (size_t)(m0 + arow) * KFC + kb;
    const float* Bp = W + (size_t)(n0 + arow) * KFC + kb;
    float4 ra0 = *(const float4*)(Ap + akq);
    float4 ra1 = *(const float4*)(Ap + akq + 4);
    float4 rb0 = *(const float4*)(Bp + akq);
    float4 rb1 = *(const float4*)(Bp + akq + 4);
    float acc[8][8] = {};
    for (int k0 = 0; k0 < kchunk; k0 += 16) {
        ra0.x = fmaxf(ra0.x, 0.f); ra0.y = fmaxf(ra0.y, 0.f);
        ra0.z = fmaxf(ra0.z, 0.f); ra0.w = fmaxf(ra0.w, 0.f);
        ra1.x = fmaxf(ra1.x, 0.f); ra1.y = fmaxf(ra1.y, 0.f);
        ra1.z = fmaxf(ra1.z, 0.f); ra1.w = fmaxf(ra1.w, 0.f);
        As[akq + 0][arow] = ra0.x; As[akq + 1][arow] = ra0.y;
        As[akq + 2][arow] = ra0.z; As[akq + 3][arow] = ra0.w;
        As[akq + 4][arow] = ra1.x; As[akq + 5][arow] = ra1.y;
        As[akq + 6][arow] = ra1.z; As[akq + 7][arow] = ra1.w;
        Bs[akq + 0][arow] = rb0.x; Bs[akq + 1][arow] = rb0.y;
        Bs[akq + 2][arow] = rb0.z; Bs[akq + 3][arow] = rb0.w;
        Bs[akq + 4][arow] = rb1.x; Bs[akq + 5][arow] = rb1.y;
        Bs[akq + 6][arow] = rb1.z; Bs[akq + 7][arow] = rb1.w;
        __syncthreads();
        int kn = k0 + 16;
        if (kn < kchunk) {
            ra0 = *(const float4*)(Ap + kn + akq);
            ra1 = *(const float4*)(Ap + kn + akq + 4);
            rb0 = *(const float4*)(Bp + kn + akq);
            rb1 = *(const float4*)(Bp + kn + akq + 4);
        }
#pragma unroll
        for (int kk = 0; kk < 16; ++kk) {
            float4 a0 = *(const float4*)&As[kk][ty * 8];
            float4 a1 = *(const float4*)&As[kk][ty * 8 + 4];
            float4 b0 = *(const float4*)&Bs[kk][tx * 8];
            float4 b1 = *(const float4*)&Bs[kk][tx * 8 + 4];
            float av[8] = {a0.x, a0.y, a0.z, a0.w, a1.x, a1.y, a1.z, a1.w};
            float bv[8] = {b0.x, b0.y, b0.z, b0.w, b1.x, b1.y, b1.z, b1.w};
#pragma unroll
            for (int i = 0; i < 8; ++i)
#pragma unroll
                for (int j = 0; j < 8; ++j) acc[i][j] += av[i] * bv[j];
        }
        __syncthreads();
    }
#pragma unroll
    for (int i = 0; i < 8; ++i) {
        int m = m0 + ty * 8 + i;
        float* o = &g_part[((size_t)z * M + m) * 256 + n0 + tx * 8];
        *(float4*)o       = make_float4(acc[i][0], acc[i][1], acc[i][2], acc[i][3]);
        *(float4*)(o + 4) = make_float4(acc[i][4], acc[i][5], acc[i][6], acc[i][7]);
    }
}

// reduce split-K partials + bias
__global__ void k_reduce(int which, const float* __restrict__ bias, int M, int Z) {
    int idx = blockIdx.x * 256 + threadIdx.x;
    if (idx >= M * 256) return;
    float s = bias[idx & 255];
    for (int z = 0; z < Z; ++z) s += g_part[(size_t)z * M * 256 + idx];
    if (which) g_O[idx] = s; else g_R[idx] = s;
}

// ---------------- K10: L2 normalize ---------------------------------------------
__global__ void k_norm(float* __restrict__ dst, int which) {
    int r = blockIdx.x, tid = threadIdx.x;
    const float* src = which ? (const float*)g_R : (const float*)g_O;
    float v = src[(size_t)r * DD + tid];
    float s = v * v;
#pragma unroll
    for (int o = 16; o > 0; o >>= 1) s += __shfl_xor_sync(0xffffffffu, s, o);
    __shared__ float ws[8];
    if ((tid & 31) == 0) ws[tid >> 5] = s;
    __syncthreads();
    float tot = 0.f;
#pragma unroll
    for (int k = 0; k < 8; ++k) tot += ws[k];
    dst[(size_t)r * DD + tid] = v * rsqrtf(tot);
}

// ---------------- launch ----------------------------------------------------------
extern "C" void kernel_launch(void* const* d_in, const int* in_sizes, int n_in,
                              void* d_out, int out_size) {
    const float* input   = (const float*)d_in[0];
    const float* objects = (const float*)d_in[1];
    const float* Wc   = (const float*)d_in[3];
    const float* bc   = (const float*)d_in[4];
    const float* Wr   = (const float*)d_in[5];
    const float* br   = (const float*)d_in[6];
    const float* Wof  = (const float*)d_in[7];
    const float* bof  = (const float*)d_in[8];
    const float* Wrf  = (const float*)d_in[9];
    const float* brf  = (const float*)d_in[10];
    const float* Wofc = (const float*)d_in[11];
    const float* bofc = (const float*)d_in[12];
    const float* Wrfc = (const float*)d_in[13];
    const float* brfc = (const float*)d_in[14];
    float* out = (float*)d_out;

    __half* wph; cudaGetSymbolAddress((void**)&wph, g_Wph);
    float* wp2;  cudaGetSymbolAddress((void**)&wp2, g_Wp2);

    k_combine<<<1024, 256>>>(Wof, Wrf, Wr, br);
    k_projT<<<dim3(8, 8, 8), 256>>>(input);
    k_geom<<<8, 256>>>(objects);
    k_poolT<<<dim3(1088, 3), 256>>>(nullptr, 2, NU, nullptr);            // union pool (profiled)
    k_pool0<<<dim3(8, 8), 224>>>(input);                                 // I0 raw
    k_ctx<<<dim3(8, 49), 256>>>(Wc, bc);
    k_KL<<<dim3(8, 2, 49), 256>>>(Wof);
    k_poolT<<<dim3(128, 1), 256>>>(objects, 1, NO, bof);                 // obj pool + epi
    k_A<<<dim3(128, 2), 256>>>(Wrf);
    k_pair<<<1088, 256>>>(brf);
    k_permWh<<<dim3(4, 256), 256>>>(Wrfc, wph);
    k_fc_tf32<<<dim3(16, 2, 8), 256>>>(2048, 1568);                      // rel FC (TF32, fp16 A+B)
    k_reduce<<<2048, 256>>>(0, brfc, 2048, 8);
    k_permW<<<dim3(4, 256), 256>>>(Wofc, wp2);
    k_fc2<<<dim3(1, 2, 16), 256>>>(wp2, 128, 784);                       // obj FC
    k_reduce<<<128, 256>>>(1, bofc, 128, 16);
    k_norm<<<128, 256>>>(out, 0);                                        // obj_out
    k_norm<<<2048, 256>>>(out + 32768, 1);                               // rel_out
    (void)in_sizes; (void)n_in; (void)out_size;
}

// round 15
// speedup vs baseline: 1.0842x; 1.0008x over previous
#include <cuda_runtime.h>
#include <cuda_fp16.h>

// ---------------- problem constants ----------------
#define BB    8
#define CCH   256
#define HWP   1024
#define NO    16
#define NPAIR 256
#define NU    136
#define P2    49
#define DD    256
#define KFC   12544
#define FCH   1024

typedef unsigned long long u64;

// ---------------- scratch ----------------
__device__ float g_M[FCH * CCH];
__device__ float g_cb[FCH];
__device__ float g_Ft[BB * HWP * FCH];                 // channel-last projected features
__device__ float g_I0[BB * CCH * P2];
__device__ float g_ctx[BB * CCH * P2];
__device__ float g_KL[BB * 2 * P2 * DD];               // [img][s][pq][d]
__device__ float g_ub[BB * NU * 4];
__device__ float g_imap[BB * NU * 2 * P2];
__device__ float g_bimap[BB * NO * P2];
__device__ float g_objf[BB * NO * P2 * DD];            // [roi][pq][d]
__device__ __half g_Ah[BB * NO * 2 * P2 * DD];         // A_sub/A_obj, fp16
__device__ __half g_Puh[BB * NU * P2 * 768];           // pooled rel, fp16
__device__ __half g_Xh[(size_t)BB * NPAIR * KFC];      // relu(rel_feat), fp16
__device__ __half g_Wph[DD * KFC];                     // Wrfc permuted, fp16
__device__ float g_Wp2[DD * KFC];                      // Wofc permuted, fp32
__device__ float g_part[8 * 2048 * 256];
__device__ float g_R[BB * NPAIR * DD];
__device__ float g_O[BB * NO * DD];

__device__ __forceinline__ float hat_int(float t) {
    t = fminf(1.f, fmaxf(-1.f, t));
    return (t < 0.f) ? 0.5f * (t + 1.f) * (t + 1.f) : 1.f - 0.5f * (1.f - t) * (1.f - t);
}

__device__ __forceinline__ unsigned f2tf32(float x) {
    unsigned r;
    asm("cvt.rna.tf32.f32 %0, %1;" : "=r"(r) : "f"(x));
    return r;
}

// ---- packed f32x2 helpers ----
__device__ __forceinline__ u64 pk2(float lo, float hi) {
    u64 r;
    asm("mov.b64 %0, {%1, %2};" : "=l"(r) : "f"(lo), "f"(hi));
    return r;
}
__device__ __forceinline__ u64 fma2(u64 a, u64 b, u64 c) {
    u64 d;
    asm("fma.rn.f32x2 %0, %1, %2, %3;" : "=l"(d) : "l"(a), "l"(b), "l"(c));
    return d;
}
__device__ __forceinline__ void upk2(u64 v, float& lo, float& hi) {
    asm("mov.b64 {%0, %1}, %2;" : "=f"(lo), "=f"(hi) : "l"(v));
}

// ---------------- K0: combine weights ------------------------------------------
__global__ void k_combine(const float* __restrict__ Wof, const float* __restrict__ Wrf,
                          const float* __restrict__ Wr, const float* __restrict__ br) {
    int row = blockIdx.x;
    int c = threadIdx.x;
    if (row < 256) {
        g_M[row * CCH + c] = Wof[row * 512 + c];
        if (c == 0) g_cb[row] = 0.f;
    } else {
        int s = (row - 256) >> 8;
        int d = (row - 256) & 255;
        const float* w = Wrf + d * 896 + 512 + s * 128;
        float acc = 0.f;
        for (int k = 0; k < 128; ++k) acc += w[k] * Wr[(s * 128 + k) * CCH + c];
        g_M[row * CCH + c] = acc;
        if (c == 0) {
            float cb = 0.f;
            for (int k = 0; k < 128; ++k) cb += w[k] * br[s * 128 + k];
            g_cb[row] = cb;
        }
    }
}

// ---------------- K1: projection GEMM (transposed output), FFMA2 ---------------
__global__ __launch_bounds__(256) void k_projT(const float* __restrict__ input) {
    __shared__ float As[16][128];   // [k][n]
    __shared__ float Bs[16][128];   // [k][m]
    int b = blockIdx.z;
    const float* In = input + (size_t)b * CCH * HWP;
    float* C = g_Ft + (size_t)b * HWP * FCH;
    int m0 = blockIdx.x * 128, n0 = blockIdx.y * 128;
    int tid = threadIdx.x;
    int tx = tid & 15, ty = tid >> 4;
    int krow = tid >> 4, ncol = (tid & 15) * 8;
    int mrow = tid >> 1, kq = (tid & 1) * 8;
    const float* Apt = In + n0 + ncol;
    const float* Bpt = g_M + (size_t)(m0 + mrow) * CCH;
    float4 ra0 = *(const float4*)(Apt + (size_t)krow * HWP);
    float4 ra1 = *(const float4*)(Apt + (size_t)krow * HWP + 4);
    float4 rb0 = *(const float4*)(Bpt + kq);
    float4 rb1 = *(const float4*)(Bpt + kq + 4);
    u64 accp[8][4];
#pragma unroll
    for (int i = 0; i < 8; ++i)
#pragma unroll
        for (int jp = 0; jp < 4; ++jp) accp[i][jp] = 0ull;
    for (int k0 = 0; k0 < CCH; k0 += 16) {
        *(float4*)&As[krow][ncol] = ra0;
        *(float4*)&As[krow][ncol + 4] = ra1;
        Bs[kq + 0][mrow] = rb0.x; Bs[kq + 1][mrow] = rb0.y;
        Bs[kq + 2][mrow] = rb0.z; Bs[kq + 3][mrow] = rb0.w;
        Bs[kq + 4][mrow] = rb1.x; Bs[kq + 5][mrow] = rb1.y;
        Bs[kq + 6][mrow] = rb1.z; Bs[kq + 7][mrow] = rb1.w;
        __syncthreads();
        int kn = k0 + 16;
        if (kn < CCH) {
            ra0 = *(const float4*)(Apt + (size_t)(kn + krow) * HWP);
            ra1 = *(const float4*)(Apt + (size_t)(kn + krow) * HWP + 4);
            rb0 = *(const float4*)(Bpt + kn + kq);
            rb1 = *(const float4*)(Bpt + kn + kq + 4);
        }
#pragma unroll
        for (int kk = 0; kk < 16; ++kk) {
            float4 a0 = *(const float4*)&As[kk][ty * 8];
            float4 a1 = *(const float4*)&As[kk][ty * 8 + 4];
            ulonglong2 bv0 = *(const ulonglong2*)&Bs[kk][tx * 8];
            ulonglong2 bv1 = *(const ulonglong2*)&Bs[kk][tx * 8 + 4];
            u64 bp[4] = {bv0.x, bv0.y, bv1.x, bv1.y};
            float av[8] = {a0.x, a0.y, a0.z, a0.w, a1.x, a1.y, a1.z, a1.w};
#pragma unroll
            for (int i = 0; i < 8; ++i) {
                u64 ap = pk2(av[i], av[i]);
#pragma unroll
                for (int jp = 0; jp < 4; ++jp)
                    accp[i][jp] = fma2(ap, bp[jp], accp[i][jp]);
            }
        }
        __syncthreads();
    }
    float4 cb0 = *(const float4*)&g_cb[m0 + tx * 8];
    float4 cb1 = *(const float4*)&g_cb[m0 + tx * 8 + 4];
    float cb[8] = {cb0.x, cb0.y, cb0.z, cb0.w, cb1.x, cb1.y, cb1.z, cb1.w};
#pragma unroll
    for (int i = 0; i < 8; ++i) {
        int n = n0 + ty * 8 + i;
        float o[8];
#pragma unroll
        for (int jp = 0; jp < 4; ++jp) upk2(accp[i][jp], o[2 * jp], o[2 * jp + 1]);
#pragma unroll
        for (int j = 0; j < 8; ++j) o[j] += cb[j];
        *(float4*)&C[(size_t)n * FCH + m0 + tx * 8]     = make_float4(o[0], o[1], o[2], o[3]);
        *(float4*)&C[(size_t)n * FCH + m0 + tx * 8 + 4] = make_float4(o[4], o[5], o[6], o[7]);
    }
}

// ---------------- K3: geometry ---------------------------------------------------
__global__ void k_geom(const float* __restrict__ objects) {
    int b = blockIdx.x;
    int tid = threadIdx.x;
    const float* obj = objects + b * NO * 4;
    __shared__ float sub[NU * 4];
    if (tid < NU) {
        int rem = tid, i = 0;
        while (rem >= NO - i) { rem -= NO - i; ++i; }
        int j = i + rem;
        float x0 = fminf(obj[i * 4 + 0], obj[j * 4 + 0]);
        float y0 = fminf(obj[i * 4 + 1], obj[j * 4 + 1]);
        float x1 = fmaxf(obj[i * 4 + 2], obj[j * 4 + 2]);
        float y1 = fmaxf(obj[i * 4 + 3], obj[j * 4 + 3]);
        sub[tid * 4 + 0] = x0; sub[tid * 4 + 1] = y0; sub[tid * 4 + 2] = x1; sub[tid * 4 + 3] = y1;
        float* gu = g_ub + (b * NU + tid) * 4;
        gu[0] = x0; gu[1] = y0; gu[2] = x1; gu[3] = y1;
    }
    __syncthreads();
    int total = (NO + NU * 2) * P2;
    for (int v = tid; v < total; v += blockDim.x) {
        int m = v / P2, pq = v - (v / P2) * P2;
        int p = pq / 7, q = pq - p * 7;
        float b1x0, b1y0, b1x1, b1y1, g0x, g0y, g1x, g1y;
        float* dst;
        if (m < NO) {
            b1x0 = obj[m * 4 + 0]; b1y0 = obj[m * 4 + 1]; b1x1 = obj[m * 4 + 2]; b1y1 = obj[m * 4 + 3];
            g0x = 0.f; g0y = 0.f; g1x = 512.f; g1y = 512.f;
            dst = &g_bimap[(b * NO + m) * P2 + pq];
        } else {
            int mm = m - NO;
            int u = mm >> 1, ab = mm & 1;
            int rem = u, i = 0;
            while (rem >= NO - i) { rem -= NO - i; ++i; }
            int j = i + rem;
            int ob = ab ? j : i;
            b1x0 = obj[ob * 4 + 0]; b1y0 = obj[ob * 4 + 1]; b1x1 = obj[ob * 4 + 2]; b1y1 = obj[ob * 4 + 3];
            g0x = sub[u * 4 + 0]; g0y = sub[u * 4 + 1]; g1x = sub[u * 4 + 2]; g1y = sub[u * 4 + 3];
            dst = &g_imap[((b * NU + u) * 2 + ab) * P2 + pq];
        }
        float bw = (g1x - g0x) * (1.f / 7.f), bh = (g1y - g0y) * (1.f / 7.f);
        float gx0 = g0x + bw * (float)q, gy0 = g0y + bh * (float)p;
        float ox = fmaxf(0.f, fminf(gx0 + bw, b1x1) - fmaxf(gx0, b1x0));
        float oy = fmaxf(0.f, fminf(gy0 + bh, b1y1) - fmaxf(gy0, b1y0));
        *dst = oy * ox / fmaxf(bw * bh, 1e-8f);
    }
}

// ---------------- channel-last pooling, FFMA2 (stable 220us form) --------------
__global__ __launch_bounds__(256, 3) void k_poolT(const float* __restrict__ boxes,
                                                  int mode, int rois_per_img,
                                                  const float* __restrict__ bof) {
    int roi = blockIdx.x;
    int cg = blockIdx.y;
    int img = roi / rois_per_img;
    const float* bp = (mode == 1) ? (boxes + roi * 4) : (g_ub + roi * 4);
    float bx0 = bp[0], by0 = bp[1], bx1 = bp[2], by1 = bp[3];
    const float s16 = 0.0625f;
    float lox = bx0 * s16, hix = bx1 * s16, loy = by0 * s16, hiy = by1 * s16;
    float bwx = (hix - lox) * (1.f / 7.f), bwy = (hiy - loy) * (1.f / 7.f);
    float inv_area = 1.f / fmaxf(bwx * bwy, 1e-8f);

    __shared__ float wx7[32][8];
    __shared__ float wy7[32][8];
    int tid = threadIdx.x;
    if (tid < 64) {
        int w = tid & 31;
        bool isy = tid >= 32;
        float lo = isy ? loy : lox;
        float bwv = isy ? bwy : bwx;
        float* dst = isy ? &wy7[w][0] : &wx7[w][0];
#pragma unroll
        for (int q = 0; q < 7; ++q) {
            float s = lo + bwv * (float)q;
            dst[q] = hat_int(s + bwv - (float)w) - hat_int(s - (float)w);
        }
        dst[7] = 0.f;
    }
    __syncthreads();

    int hmin = max(0, (int)ceilf(loy - 1.f));
    int hmax = min(31, (int)floorf(hiy + 1.f));
    int wmin = max(0, (int)ceilf(lox - 1.f));
    int wmax = min(31, (int)floorf(hix + 1.f));

    int ch_off = (mode == 2) ? (256 + cg * 256) : 0;
    const float* Fp = g_Ft + (size_t)img * HWP * FCH + ch_off + tid;

    u64 acc2[7][4];
#pragma unroll
    for (int p = 0; p < 7; ++p)
#pragma unroll
        for (int k = 0; k < 4; ++k) acc2[p][k] = 0ull;

    for (int h = hmin; h <= hmax; ++h) {
        u64 tq2[4] = {0ull, 0ull, 0ull, 0ull};
        const float* Fh = Fp + (size_t)(h * 32) * FCH;
        for (int w = wmin; w <= wmax; ++w) {
            float f = Fh[(size_t)w * FCH];
            u64 ff = pk2(f, f);
            ulonglong2 wa = *(const ulonglong2*)&wx7[w][0];
            ulonglong2 wb = *(const ulonglong2*)&wx7[w][4];
            tq2[0] = fma2(ff, wa.x, tq2[0]);
            tq2[1] = fma2(ff, wa.y, tq2[1]);
            tq2[2] = fma2(ff, wb.x, tq2[2]);
            tq2[3] = fma2(ff, wb.y, tq2[3]);
        }
#pragma unroll
        for (int p = 0; p < 7; ++p) {
            float wyv = wy7[h][p];
            u64 wyp = pk2(wyv, wyv);
#pragma unroll
            for (int k = 0; k < 4; ++k) acc2[p][k] = fma2(wyp, tq2[k], acc2[p][k]);
        }
    }

    if (mode == 2) {
        __half* o = g_Puh + (size_t)roi * P2 * 768 + cg * 256 + tid;
#pragma unroll
        for (int p = 0; p < 7; ++p) {
            float aq[8];
#pragma unroll
            for (int k = 0; k < 4; ++k) upk2(acc2[p][k], aq[2 * k], aq[2 * k + 1]);
#pragma unroll
            for (int q = 0; q < 7; ++q)
                o[(size_t)(p * 7 + q) * 768] = __float2half(aq[q] * inv_area);
        }
    } else {
        const float* K = g_KL + ((size_t)(img * 2 + 0) * P2) * DD + tid;
        const float* L = g_KL + ((size_t)(img * 2 + 1) * P2) * DD + tid;
        const float* bm = g_bimap + (size_t)roi * P2;
        float bv = bof[tid];
        float* o = g_objf + (size_t)roi * P2 * DD + tid;
#pragma unroll
        for (int p = 0; p < 7; ++p) {
            float aq[8];
#pragma unroll
            for (int k = 0; k < 4; ++k) upk2(acc2[p][k], aq[2 * k], aq[2 * k + 1]);
#pragma unroll
            for (int q = 0; q < 7; ++q) {
                int pq = p * 7 + q;
                o[(size_t)pq * DD] = aq[q] * inv_area + K[(size_t)pq * DD]
                                   + L[(size_t)pq * DD] * bm[pq] + bv;
            }
        }
    }
}

// ---------------- mode-0 pool: raw input full-image box -> g_I0 ----------------
__global__ void k_pool0(const float* __restrict__ src) {
    int img = blockIdx.x;
    int c0 = blockIdx.y * 32;
    float lox = 0.f, loy = 0.f;
    float bwx = 32.f / 7.f, bwy = 32.f / 7.f;
    __shared__ float sWx[224], sWy[224], tile[2][32 * 33];
    int tid = threadIdx.x;
    {
        int p = tid >> 5, i = tid & 31;
        float sx = lox + bwx * (float)p;
        sWx[tid] = hat_int(sx + bwx - (float)i) - hat_int(sx - (float)i);
        float sy = loy + bwy * (float)p;
        sWy[tid] = hat_int(sy + bwy - (float)i) - hat_int(sy - (float)i);
    }
    const float* Fp = src + (size_t)img * CCH * HWP + (size_t)c0 * HWP;
    for (int e = tid; e < 1024; e += 224) {
        int cc = e >> 5, w = e & 31;
        tile[0][cc * 33 + w] = Fp[(size_t)cc * HWP + w];
    }
    int c = tid & 31, q = tid >> 5;
    float acc[7] = {};
    for (int h = 0; h < 32; ++h) {
        __syncthreads();
        if (h < 31) {
            int hb = (h + 1) & 1;
            for (int e = tid; e < 1024; e += 224) {
                int cc = e >> 5, w = e & 31;
                tile[hb][cc * 33 + w] = Fp[(size_t)cc * HWP + (h + 1) * 32 + w];
            }
        }
        float t = 0.f;
        const float* wx = &sWx[q * 32];
        const float* tr = &tile[h & 1][c * 33];
        for (int w = 0; w < 32; ++w) t += tr[w] * wx[w];
#pragma unroll
        for (int p = 0; p < 7; ++p) acc[p] += t * sWy[p * 32 + h];
    }
    int d = c0 + c;
    float* o = g_I0 + ((size_t)img * CCH + d) * P2;
#pragma unroll
    for (int p = 0; p < 7; ++p) o[p * 7 + q] = acc[p];
}

// ---------------- K2b: ctx_pool --------------------------------------------------
__global__ void k_ctx(const float* __restrict__ Wc, const float* __restrict__ bc) {
    int b = blockIdx.x, pq = blockIdx.y;
    int c = threadIdx.x;
    __shared__ float S;
    if (c == 0) {
        int p = pq / 7, q = pq - p * 7;
        float bw = 32.f / 7.f;
        float sx = 0.f, sy = 0.f;
        float st = bw * q, en = st + bw;
        for (int i = 0; i < 32; ++i) sx += hat_int(en - (float)i) - hat_int(st - (float)i);
        st = bw * p; en = st + bw;
        for (int i = 0; i < 32; ++i) sy += hat_int(en - (float)i) - hat_int(st - (float)i);
        S = sx * sy;
    }
    __syncthreads();
    float acc = 0.f;
    const float* I = g_I0 + (size_t)b * CCH * P2 + pq;
    const float* w = Wc + c * CCH;
    for (int k = 0; k < CCH; ++k) acc += w[k] * I[k * P2];
    const float inv_area = (7.f * 7.f) / (32.f * 32.f);
    g_ctx[((size_t)b * CCH + c) * P2 + pq] = (acc + bc[c] * S) * inv_area;
}

// ---------------- K2c: K/L images, layout [img][s][pq][d] ----------------------
__global__ void k_KL(const float* __restrict__ Wof) {
    int b = blockIdx.x, s = blockIdx.y, pq = blockIdx.z;
    int d = threadIdx.x;
    float acc = 0.f;
    const float* w = Wof + d * 512 + 256 + s * 128;
    const float* x = g_ctx + ((size_t)b * CCH + s * 128) * P2 + pq;
    for (int k = 0; k < 128; ++k) acc += w[k] * x[k * P2];
    g_KL[((size_t)(b * 2 + s) * P2 + pq) * DD + d] = acc;
}

// ---------------- K6: A_sub/A_obj (fp16 out), layouts [roi][pq][d] -------------
__global__ void k_A(const float* __restrict__ Wrf) {
    int bi = blockIdx.x;
    int s = blockIdx.y;
    int d = threadIdx.x;
    __shared__ float Xs[64 * 49];   // [kl][pq]
    const float* X = g_objf + (size_t)bi * P2 * DD;   // [pq][k]
    const float* w = Wrf + d * 896 + s * 256;
    float acc[P2];
#pragma unroll
    for (int pq = 0; pq < P2; ++pq) acc[pq] = 0.f;
    for (int k0 = 0; k0 < 256; k0 += 64) {
        __syncthreads();
        for (int e = d; e < 64 * 49; e += 256) {
            int pq = e >> 6, kl = e & 63;
            Xs[kl * 49 + pq] = X[pq * 256 + k0 + kl];
        }
        __syncthreads();
        for (int kl = 0; kl < 64; ++kl) {
            float wv = w[k0 + kl];
            const float* xr = &Xs[kl * 49];
#pragma unroll
            for (int pq = 0; pq < P2; ++pq) acc[pq] += wv * xr[pq];
        }
    }
    __half* o = g_Ah + (((size_t)bi * 2 + s) * P2) * DD + d;
#pragma unroll
    for (int pq = 0; pq < P2; ++pq) o[(size_t)pq * DD] = __float2half(acc[pq]);
}

// ---------------- K7: pair assembly + relu, __half2 d-pairs, 128 threads --------
__global__ void k_pair(const float* __restrict__ brf) {
    int bu = blockIdx.x;            // b*NU + u
    int b = bu / NU, u = bu - b * NU;
    int rem = u, i = 0;
    while (rem >= NO - i) { rem -= NO - i; ++i; }
    int j = i + rem;                // i <= j
    __shared__ float imA[P2], imB[P2];
    int tid = threadIdx.x;          // 0..127, owns d = 2*tid, 2*tid+1
    if (tid < P2) {
        imA[tid] = g_imap[((size_t)bu * 2 + 0) * P2 + tid];
        imB[tid] = g_imap[((size_t)bu * 2 + 1) * P2 + tid];
    }
    __syncthreads();
    const __half2* Ai_s = (const __half2*)(g_Ah + ((size_t)(b * NO + i) * 2 + 0) * P2 * DD) + tid;
    const __half2* Ai_o = (const __half2*)(g_Ah + ((size_t)(b * NO + i) * 2 + 1) * P2 * DD) + tid;
    const __half2* Aj_s = (const __half2*)(g_Ah + ((size_t)(b * NO + j) * 2 + 0) * P2 * DD) + tid;
    const __half2* Aj_o = (const __half2*)(g_Ah + ((size_t)(b * NO + j) * 2 + 1) * P2 * DD) + tid;
    const __half2* Pu = (const __half2*)(g_Puh + (size_t)bu * P2 * 768) + tid;
    __half2* X0 = (__half2*)(g_Xh + (size_t)(b * NPAIR + i * NO + j) * KFC) + tid;
    __half2* X1 = (__half2*)(g_Xh + (size_t)(b * NPAIR + j * NO + i) * KFC) + tid;
    float2 bv = *(const float2*)&brf[tid * 2];
    bool diag = (i == j);
#pragma unroll 1
    for (int pq = 0; pq < P2; ++pq) {
        float ia = imA[pq], ib = imB[pq];
        float2 x = __half22float2(Pu[pq * 384]);
        float2 y = __half22float2(Pu[pq * 384 + 128]);
        float2 z = __half22float2(Pu[pq * 384 + 256]);
        float2 as0 = __half22float2(Ai_s[pq * 128]);
        float2 ao1 = __half22float2(Aj_o[pq * 128]);
        float v0x = as0.x + ao1.x + x.x + ia * y.x + ib * z.x + bv.x;
        float v0y = as0.y + ao1.y + x.y + ia * y.y + ib * z.y + bv.y;
        X0[pq * 128] = __floats2half2_rn(fmaxf(v0x, 0.f), fmaxf(v0y, 0.f));
        if (!diag) {
            float2 as1 = __half22float2(Aj_s[pq * 128]);
            float2 ao0 = __half22float2(Ai_o[pq * 128]);
            float v1x = as1.x + ao0.x + x.x + ib * y.x + ia * z.x + bv.x;
            float v1y = as1.y + ao0.y + x.y + ib * y.y + ia * z.y + bv.y;
            X1[pq * 128] = __floats2half2_rn(fmaxf(v1x, 0.f), fmaxf(v1y, 0.f));
        }
    }
}

// ---------------- weight permutations --------------------------------------------
__global__ void k_permWh(const float* __restrict__ W, __half* __restrict__ dst) {
    __shared__ float s[64 * 49];
    int dg = blockIdx.x;
    int n = blockIdx.y;
    int tid = threadIdx.x;
    const float* src = W + (size_t)n * KFC + dg * 64 * 49;
    for (int e = tid; e < 64 * 49; e += 256) s[e] = src[e];
    __syncthreads();
    __half* o = dst + (size_t)n * KFC + dg * 64;
    for (int e = tid; e < 64 * 49; e += 256) {
        int pq = e >> 6, dl = e & 63;
        o[(size_t)pq * 256 + dl] = __float2half(s[dl * 49 + pq]);
    }
}
__global__ void k_permW(const float* __restrict__ W, float* __restrict__ dst) {
    __shared__ float s[64 * 49];
    int dg = blockIdx.x;
    int n = blockIdx.y;
    int tid = threadIdx.x;
    const float* src = W + (size_t)n * KFC + dg * 64 * 49;
    for (int e = tid; e < 64 * 49; e += 256) s[e] = src[e];
    __syncthreads();
    float* o = dst + (size_t)n * KFC + dg * 64;
    for (int e = tid; e < 64 * 49; e += 256) {
        int pq = e >> 6, dl = e & 63;
        o[(size_t)pq * 256 + dl] = s[dl * 49 + pq];
    }
}

// ---------------- rel FC: TF32 MMA, A and B read from fp16, split-K ------------
__global__ __launch_bounds__(256) void k_fc_tf32(int M, int kchunk) {
    __shared__ unsigned As[16][136];
    __shared__ unsigned Bs[16][136];
    int m0 = blockIdx.x * 128, n0 = blockIdx.y * 128, z = blockIdx.z;
    int kb = z * kchunk;
    int tid = threadIdx.x;
    int row = tid >> 1, kq = (tid & 1) * 8;
    const __half* Ap = g_Xh + (size_t)(m0 + row) * KFC + kb + kq;
    const __half* Bp = g_Wph + (size_t)(n0 + row) * KFC + kb + kq;
    int lane = tid & 31;
    int g = lane >> 2, tg = lane & 3;
    int warp = tid >> 5;
    int wm = (warp & 3) * 32, wn = (warp >> 2) * 64;

    float acc[2][8][4];
#pragma unroll
    for (int mi = 0; mi < 2; ++mi)
#pragma unroll
        for (int nj = 0; nj < 8; ++nj)
#pragma unroll
            for (int r = 0; r < 4; ++r) acc[mi][nj][r] = 0.f;

    uint4 rah = *(const uint4*)(Ap);
    uint4 rbh = *(const uint4*)(Bp);

    for (int k0 = 0; k0 < kchunk; k0 += 16) {
        {
            float2 f0 = __half22float2(*(__half2*)&rah.x), f1 = __half22float2(*(__half2*)&rah.y);
            float2 f2 = __half22float2(*(__half2*)&rah.z), f3 = __half22float2(*(__half2*)&rah.w);
            As[kq + 0][row] = f2tf32(f0.x); As[kq + 1][row] = f2tf32(f0.y);
            As[kq + 2][row] = f2tf32(f1.x); As[kq + 3][row] = f2tf32(f1.y);
            As[kq + 4][row] = f2tf32(f2.x); As[kq + 5][row] = f2tf32(f2.y);
            As[kq + 6][row] = f2tf32(f3.x); As[kq + 7][row] = f2tf32(f3.y);
        }
        {
            float2 f0 = __half22float2(*(__half2*)&rbh.x), f1 = __half22float2(*(__half2*)&rbh.y);
            float2 f2 = __half22float2(*(__half2*)&rbh.z), f3 = __half22float2(*(__half2*)&rbh.w);
            Bs[kq + 0][row] = f2tf32(f0.x); Bs[kq + 1][row] = f2tf32(f0.y);
            Bs[kq + 2][row] = f2tf32(f1.x); Bs[kq + 3][row] = f2tf32(f1.y);
            Bs[kq + 4][row] = f2tf32(f2.x); Bs[kq + 5][row] = f2tf32(f2.y);
            Bs[kq + 6][row] = f2tf32(f3.x); Bs[kq + 7][row] = f2tf32(f3.y);
        }
        __syncthreads();
        int kn = k0 + 16;
        if (kn < kchunk) {
            rah = *(const uint4*)(Ap + kn);
            rbh = *(const uint4*)(Bp + kn);
        }
#pragma unroll
        for (int kk = 0; kk < 16; kk += 8) {
            unsigned af[2][4];
#pragma unroll
            for (int mi = 0; mi < 2; ++mi) {
                int mb = wm + mi * 16;
                af[mi][0] = As[kk + tg][mb + g];
                af[mi][1] = As[kk + tg][mb + g + 8];
                af[mi][2] = As[kk + tg + 4][mb + g];
                af[mi][3] = As[kk + tg + 4][mb + g + 8];
            }
            unsigned bf[8][2];
#pragma unroll
            for (int nj = 0; nj < 8; ++nj) {
                bf[nj][0] = Bs[kk + tg][wn + nj * 8 + g];
                bf[nj][1] = Bs[kk + tg + 4][wn + nj * 8 + g];
            }
#pragma unroll
            for (int mi = 0; mi < 2; ++mi)
#pragma unroll
                for (int nj = 0; nj < 8; ++nj) {
                    asm volatile(
                        "mma.sync.aligned.m16n8k8.row.col.f32.tf32.tf32.f32 "
                        "{%0,%1,%2,%3},{%4,%5,%6,%7},{%8,%9},{%0,%1,%2,%3};"
                        : "+f"(acc[mi][nj][0]), "+f"(acc[mi][nj][1]),
                          "+f"(acc[mi][nj][2]), "+f"(acc[mi][nj][3])
                        : "r"(af[mi][0]), "r"(af[mi][1]), "r"(af[mi][2]), "r"(af[mi][3]),
                          "r"(bf[nj][0]), "r"(bf[nj][1]));
                }
        }
        __syncthreads();
    }
#pragma unroll
    for (int mi = 0; mi < 2; ++mi) {
        int m = m0 + wm + mi * 16 + g;
#pragma unroll
        for (int nj = 0; nj < 8; ++nj) {
            int n = n0 + wn + nj * 8 + 2 * tg;
            float* p0 = &g_part[((size_t)z * M + m) * 256 + n];
            float* p1 = &g_part[((size_t)z * M + m + 8) * 256 + n];
            *(float2*)p0 = make_float2(acc[mi][nj][0], acc[mi][nj][1]);
            *(float2*)p1 = make_float2(acc[mi][nj][2], acc[mi][nj][3]);
        }
    }
}

// ---------------- obj FC: fp32 SIMT, split-K, relu at load ----------------------
__global__ __launch_bounds__(256) void k_fc2(const float* __restrict__ W,
                                             int M, int kchunk) {
    __shared__ float As[16][128];
    __shared__ float Bs[16][128];
    const float* A = (const float*)g_objf;
    int m0 = blockIdx.x * 128, n0 = blockIdx.y * 128, z = blockIdx.z;
    int kb = z * kchunk;
    int tid = threadIdx.x;
    int tx = tid & 15, ty = tid >> 4;
    int arow = tid >> 1, akq = (tid & 1) * 8;
    const float* Ap = A + (size_t)(m0 + arow) * KFC + kb;
    const float* Bp = W + (size_t)(n0 + arow) * KFC + kb;
    float4 ra0 = *(const float4*)(Ap + akq);
    float4 ra1 = *(const float4*)(Ap + akq + 4);
    float4 rb0 = *(const float4*)(Bp + akq);
    float4 rb1 = *(const float4*)(Bp + akq + 4);
    float acc[8][8] = {};
    for (int k0 = 0; k0 < kchunk; k0 += 16) {
        ra0.x = fmaxf(ra0.x, 0.f); ra0.y = fmaxf(ra0.y, 0.f);
        ra0.z = fmaxf(ra0.z, 0.f); ra0.w = fmaxf(ra0.w, 0.f);
        ra1.x = fmaxf(ra1.x, 0.f); ra1.y = fmaxf(ra1.y, 0.f);
        ra1.z = fmaxf(ra1.z, 0.f); ra1.w = fmaxf(ra1.w, 0.f);
        As[akq + 0][arow] = ra0.x; As[akq + 1][arow] = ra0.y;
        As[akq + 2][arow] = ra0.z; As[akq + 3][arow] = ra0.w;
        As[akq + 4][arow] = ra1.x; As[akq + 5][arow] = ra1.y;
        As[akq + 6][arow] = ra1.z; As[akq + 7][arow] = ra1.w;
        Bs[akq + 0][arow] = rb0.x; Bs[akq + 1][arow] = rb0.y;
        Bs[akq + 2][arow] = rb0.z; Bs[akq + 3][arow] = rb0.w;
        Bs[akq + 4][arow] = rb1.x; Bs[akq + 5][arow] = rb1.y;
        Bs[akq + 6][arow] = rb1.z; Bs[akq + 7][arow] = rb1.w;
        __syncthreads();
        int kn = k0 + 16;
        if (kn < kchunk) {
            ra0 = *(const float4*)(Ap + kn + akq);
            ra1 = *(const float4*)(Ap + kn + akq + 4);
            rb0 = *(const float4*)(Bp + kn + akq);
            rb1 = *(const float4*)(Bp + kn + akq + 4);
        }
#pragma unroll
        for (int kk = 0; kk < 16; ++kk) {
            float4 a0 = *(const float4*)&As[kk][ty * 8];
            float4 a1 = *(const float4*)&As[kk][ty * 8 + 4];
            float4 b0 = *(const float4*)&Bs[kk][tx * 8];
            float4 b1 = *(const float4*)&Bs[kk][tx * 8 + 4];
            float av[8] = {a0.x, a0.y, a0.z, a0.w, a1.x, a1.y, a1.z, a1.w};
            float bv[8] = {b0.x, b0.y, b0.z, b0.w, b1.x, b1.y, b1.z, b1.w};
#pragma unroll
            for (int i = 0; i < 8; ++i)
#pragma unroll
                for (int j = 0; j < 8; ++j) acc[i][j] += av[i] * bv[j];
        }
        __syncthreads();
    }
#pragma unroll
    for (int i = 0; i < 8; ++i) {
        int m = m0 + ty * 8 + i;
        float* o = &g_part[((size_t)z * M + m) * 256 + n0 + tx * 8];
        *(float4*)o       = make_float4(acc[i][0], acc[i][1], acc[i][2], acc[i][3]);
        *(float4*)(o + 4) = make_float4(acc[i][4], acc[i][5], acc[i][6], acc[i][7]);
    }
}

// reduce split-K partials + bias
__global__ void k_reduce(int which, const float* __restrict__ bias, int M, int Z) {
    int idx = blockIdx.x * 256 + threadIdx.x;
    if (idx >= M * 256) return;
    float s = bias[idx & 255];
    for (int z = 0; z < Z; ++z) s += g_part[(size_t)z * M * 256 + idx];
    if (which) g_O[idx] = s; else g_R[idx] = s;
}

// ---------------- K10: L2 normalize ---------------------------------------------
__global__ void k_norm(float* __restrict__ dst, int which) {
    int r = blockIdx.x, tid = threadIdx.x;
    const float* src = which ? (const float*)g_R : (const float*)g_O;
    float v = src[(size_t)r * DD + tid];
    float s = v * v;
#pragma unroll
    for (int o = 16; o > 0; o >>= 1) s += __shfl_xor_sync(0xffffffffu, s, o);
    __shared__ float ws[8];
    if ((tid & 31) == 0) ws[tid >> 5] = s;
    __syncthreads();
    float tot = 0.f;
#pragma unroll
    for (int k = 0; k < 8; ++k) tot += ws[k];
    dst[(size_t)r * DD + tid] = v * rsqrtf(tot);
}

// ---------------- launch ----------------------------------------------------------
extern "C" void kernel_launch(void* const* d_in, const int* in_sizes, int n_in,
                              void* d_out, int out_size) {
    const float* input   = (const float*)d_in[0];
    const float* objects = (const float*)d_in[1];
    const float* Wc   = (const float*)d_in[3];
    const float* bc   = (const float*)d_in[4];
    const float* Wr   = (const float*)d_in[5];
    const float* br   = (const float*)d_in[6];
    const float* Wof  = (const float*)d_in[7];
    const float* bof  = (const float*)d_in[8];
    const float* Wrf  = (const float*)d_in[9];
    const float* brf  = (const float*)d_in[10];
    const float* Wofc = (const float*)d_in[11];
    const float* bofc = (const float*)d_in[12];
    const float* Wrfc = (const float*)d_in[13];
    const float* brfc = (const float*)d_in[14];
    float* out = (float*)d_out;

    __half* wph; cudaGetSymbolAddress((void**)&wph, g_Wph);
    float* wp2;  cudaGetSymbolAddress((void**)&wp2, g_Wp2);

    // profiled slot (4th launch) now audits k_projT
    k_combine<<<1024, 256>>>(Wof, Wrf, Wr, br);
    k_geom<<<8, 256>>>(objects);
    k_pool0<<<dim3(8, 8), 224>>>(input);                                 // I0 raw
    k_projT<<<dim3(8, 8, 8), 256>>>(input);                              // <-- profiled
    k_poolT<<<dim3(1088, 3), 256>>>(nullptr, 2, NU, nullptr);            // union pool
    k_ctx<<<dim3(8, 49), 256>>>(Wc, bc);
    k_KL<<<dim3(8, 2, 49), 256>>>(Wof);
    k_poolT<<<dim3(128, 1), 256>>>(objects, 1, NO, bof);                 // obj pool + epi
    k_A<<<dim3(128, 2), 256>>>(Wrf);
    k_pair<<<1088, 128>>>(brf);
    k_permWh<<<dim3(4, 256), 256>>>(Wrfc, wph);
    k_fc_tf32<<<dim3(16, 2, 8), 256>>>(2048, 1568);                      // rel FC (TF32, fp16 A+B)
    k_reduce<<<2048, 256>>>(0, brfc, 2048, 8);
    k_permW<<<dim3(4, 256), 256>>>(Wofc, wp2);
    k_fc2<<<dim3(1, 2, 16), 256>>>(wp2, 128, 784);                       // obj FC
    k_reduce<<<128, 256>>>(1, bofc, 128, 16);
    k_norm<<<128, 256>>>(out, 0);                                        // obj_out
    k_norm<<<2048, 256>>>(out + 32768, 1);                               // rel_out
    (void)in_sizes; (void)n_in; (void)out_size;
}

// round 16
// speedup vs baseline: 1.1412x; 1.0526x over previous
#include <cuda_runtime.h>
#include <cuda_fp16.h>

// ---------------- problem constants ----------------
#define BB    8
#define CCH   256
#define HWP   1024
#define NO    16
#define NPAIR 256
#define NU    136
#define P2    49
#define DD    256
#define KFC   12544
#define FCH   1024

typedef unsigned long long u64;

// ---------------- scratch ----------------
__device__ float g_M[FCH * CCH];
__device__ float g_cb[FCH];
__device__ float g_Ft[BB * HWP * FCH];                 // channel-last projected features
__device__ float g_I0[BB * CCH * P2];
__device__ float g_ctx[BB * CCH * P2];
__device__ float g_KL[BB * 2 * P2 * DD];               // [img][s][pq][d]
__device__ float g_ub[BB * NU * 4];
__device__ float g_imap[BB * NU * 2 * P2];
__device__ float g_bimap[BB * NO * P2];
__device__ float g_objf[BB * NO * P2 * DD];            // [roi][pq][d]
__device__ __half g_Ah[BB * NO * 2 * P2 * DD];         // A_sub/A_obj, fp16
__device__ __half g_Puh[BB * NU * P2 * 768];           // pooled rel, fp16
__device__ __half g_Xh[(size_t)BB * NPAIR * KFC];      // relu(rel_feat), fp16
__device__ __half g_Wph[DD * KFC];                     // Wrfc permuted, fp16
__device__ float g_Wp2[DD * KFC];                      // Wofc permuted, fp32
__device__ float g_part[8 * 2048 * 256];
__device__ float g_R[BB * NPAIR * DD];
__device__ float g_O[BB * NO * DD];

__device__ __forceinline__ float hat_int(float t) {
    t = fminf(1.f, fmaxf(-1.f, t));
    return (t < 0.f) ? 0.5f * (t + 1.f) * (t + 1.f) : 1.f - 0.5f * (1.f - t) * (1.f - t);
}

__device__ __forceinline__ unsigned f2tf32(float x) {
    unsigned r;
    asm("cvt.rna.tf32.f32 %0, %1;" : "=r"(r) : "f"(x));
    return r;
}

// ---- packed f32x2 helpers ----
__device__ __forceinline__ u64 pk2(float lo, float hi) {
    u64 r;
    asm("mov.b64 %0, {%1, %2};" : "=l"(r) : "f"(lo), "f"(hi));
    return r;
}
__device__ __forceinline__ u64 fma2(u64 a, u64 b, u64 c) {
    u64 d;
    asm("fma.rn.f32x2 %0, %1, %2, %3;" : "=l"(d) : "l"(a), "l"(b), "l"(c));
    return d;
}
__device__ __forceinline__ void upk2(u64 v, float& lo, float& hi) {
    asm("mov.b64 {%0, %1}, %2;" : "=f"(lo), "=f"(hi) : "l"(v));
}

// ---------------- K0: combine weights ------------------------------------------
__global__ void k_combine(const float* __restrict__ Wof, const float* __restrict__ Wrf,
                          const float* __restrict__ Wr, const float* __restrict__ br) {
    int row = blockIdx.x;
    int c = threadIdx.x;
    if (row < 256) {
        g_M[row * CCH + c] = Wof[row * 512 + c];
        if (c == 0) g_cb[row] = 0.f;
    } else {
        int s = (row - 256) >> 8;
        int d = (row - 256) & 255;
        const float* w = Wrf + d * 896 + 512 + s * 128;
        float acc = 0.f;
        for (int k = 0; k < 128; ++k) acc += w[k] * Wr[(s * 128 + k) * CCH + c];
        g_M[row * CCH + c] = acc;
        if (c == 0) {
            float cb = 0.f;
            for (int k = 0; k < 128; ++k) cb += w[k] * br[s * 128 + k];
            g_cb[row] = cb;
        }
    }
}

// ---------------- K1: projection GEMM, TF32 MMA, output g_Ft[n][m] -------------
// C[n][m] = sum_k input[b][k][n] * g_M[m][k] + cb[m]
__global__ __launch_bounds__(256) void k_projT_mma(const float* __restrict__ input) {
    __shared__ unsigned As[16][136];   // [k][n]
    __shared__ unsigned Bs[16][136];   // [k][m]
    int b = blockIdx.z;
    const float* In = input + (size_t)b * CCH * HWP;
    float* C = g_Ft + (size_t)b * HWP * FCH;
    int nt0 = blockIdx.x * 128, mt0 = blockIdx.y * 128;
    int tid = threadIdx.x;
    // A loads: [16 k][128 n], coalesced in n
    int krow = tid >> 4, ncol = (tid & 15) * 8;
    // B loads: [128 m][16 k] from g_M, coalesced in k
    int mrow = tid >> 1, kq = (tid & 1) * 8;
    const float* Apt = In + nt0 + ncol;
    const float* Bpt = g_M + (size_t)(mt0 + mrow) * CCH;
    int lane = tid & 31;
    int g = lane >> 2, tg = lane & 3;
    int warp = tid >> 5;
    int wm = (warp & 3) * 32;   // n-dim warp tile
    int wn = (warp >> 2) * 64;  // m-dim warp tile

    float acc[2][8][4];
#pragma unroll
    for (int mi = 0; mi < 2; ++mi)
#pragma unroll
        for (int nj = 0; nj < 8; ++nj)
#pragma unroll
            for (int r = 0; r < 4; ++r) acc[mi][nj][r] = 0.f;

    float4 ra0 = *(const float4*)(Apt + (size_t)krow * HWP);
    float4 ra1 = *(const float4*)(Apt + (size_t)krow * HWP + 4);
    float4 rb0 = *(const float4*)(Bpt + kq);
    float4 rb1 = *(const float4*)(Bpt + kq + 4);

    for (int k0 = 0; k0 < CCH; k0 += 16) {
        {
            uint4 v0 = make_uint4(f2tf32(ra0.x), f2tf32(ra0.y), f2tf32(ra0.z), f2tf32(ra0.w));
            uint4 v1 = make_uint4(f2tf32(ra1.x), f2tf32(ra1.y), f2tf32(ra1.z), f2tf32(ra1.w));
            *(uint4*)&As[krow][ncol] = v0;
            *(uint4*)&As[krow][ncol + 4] = v1;
        }
        Bs[kq + 0][mrow] = f2tf32(rb0.x); Bs[kq + 1][mrow] = f2tf32(rb0.y);
        Bs[kq + 2][mrow] = f2tf32(rb0.z); Bs[kq + 3][mrow] = f2tf32(rb0.w);
        Bs[kq + 4][mrow] = f2tf32(rb1.x); Bs[kq + 5][mrow] = f2tf32(rb1.y);
        Bs[kq + 6][mrow] = f2tf32(rb1.z); Bs[kq + 7][mrow] = f2tf32(rb1.w);
        __syncthreads();
        int kn = k0 + 16;
        if (kn < CCH) {
            ra0 = *(const float4*)(Apt + (size_t)(kn + krow) * HWP);
            ra1 = *(const float4*)(Apt + (size_t)(kn + krow) * HWP + 4);
            rb0 = *(const float4*)(Bpt + kn + kq);
            rb1 = *(const float4*)(Bpt + kn + kq + 4);
        }
#pragma unroll
        for (int kk = 0; kk < 16; kk += 8) {
            unsigned af[2][4];
#pragma unroll
            for (int mi = 0; mi < 2; ++mi) {
                int nb = wm + mi * 16;
                af[mi][0] = As[kk + tg][nb + g];
                af[mi][1] = As[kk + tg][nb + g + 8];
                af[mi][2] = As[kk + tg + 4][nb + g];
                af[mi][3] = As[kk + tg + 4][nb + g + 8];
            }
            unsigned bf[8][2];
#pragma unroll
            for (int nj = 0; nj < 8; ++nj) {
                bf[nj][0] = Bs[kk + tg][wn + nj * 8 + g];
                bf[nj][1] = Bs[kk + tg + 4][wn + nj * 8 + g];
            }
#pragma unroll
            for (int mi = 0; mi < 2; ++mi)
#pragma unroll
                for (int nj = 0; nj < 8; ++nj) {
                    asm volatile(
                        "mma.sync.aligned.m16n8k8.row.col.f32.tf32.tf32.f32 "
                        "{%0,%1,%2,%3},{%4,%5,%6,%7},{%8,%9},{%0,%1,%2,%3};"
                        : "+f"(acc[mi][nj][0]), "+f"(acc[mi][nj][1]),
                          "+f"(acc[mi][nj][2]), "+f"(acc[mi][nj][3])
                        : "r"(af[mi][0]), "r"(af[mi][1]), "r"(af[mi][2]), "r"(af[mi][3]),
                          "r"(bf[nj][0]), "r"(bf[nj][1]));
                }
        }
        __syncthreads();
    }
#pragma unroll
    for (int mi = 0; mi < 2; ++mi) {
        int n = nt0 + wm + mi * 16 + g;
#pragma unroll
        for (int nj = 0; nj < 8; ++nj) {
            int m = mt0 + wn + nj * 8 + 2 * tg;
            float2 cb = *(const float2*)&g_cb[m];
            float* p0 = &C[(size_t)n * FCH + m];
            float* p1 = &C[(size_t)(n + 8) * FCH + m];
            *(float2*)p0 = make_float2(acc[mi][nj][0] + cb.x, acc[mi][nj][1] + cb.y);
            *(float2*)p1 = make_float2(acc[mi][nj][2] + cb.x, acc[mi][nj][3] + cb.y);
        }
    }
}

// ---------------- K3: geometry ---------------------------------------------------
__global__ void k_geom(const float* __restrict__ objects) {
    int b = blockIdx.x;
    int tid = threadIdx.x;
    const float* obj = objects + b * NO * 4;
    __shared__ float sub[NU * 4];
    if (tid < NU) {
        int rem = tid, i = 0;
        while (rem >= NO - i) { rem -= NO - i; ++i; }
        int j = i + rem;
        float x0 = fminf(obj[i * 4 + 0], obj[j * 4 + 0]);
        float y0 = fminf(obj[i * 4 + 1], obj[j * 4 + 1]);
        float x1 = fmaxf(obj[i * 4 + 2], obj[j * 4 + 2]);
        float y1 = fmaxf(obj[i * 4 + 3], obj[j * 4 + 3]);
        sub[tid * 4 + 0] = x0; sub[tid * 4 + 1] = y0; sub[tid * 4 + 2] = x1; sub[tid * 4 + 3] = y1;
        float* gu = g_ub + (b * NU + tid) * 4;
        gu[0] = x0; gu[1] = y0; gu[2] = x1; gu[3] = y1;
    }
    __syncthreads();
    int total = (NO + NU * 2) * P2;
    for (int v = tid; v < total; v += blockDim.x) {
        int m = v / P2, pq = v - (v / P2) * P2;
        int p = pq / 7, q = pq - p * 7;
        float b1x0, b1y0, b1x1, b1y1, g0x, g0y, g1x, g1y;
        float* dst;
        if (m < NO) {
            b1x0 = obj[m * 4 + 0]; b1y0 = obj[m * 4 + 1]; b1x1 = obj[m * 4 + 2]; b1y1 = obj[m * 4 + 3];
            g0x = 0.f; g0y = 0.f; g1x = 512.f; g1y = 512.f;
            dst = &g_bimap[(b * NO + m) * P2 + pq];
        } else {
            int mm = m - NO;
            int u = mm >> 1, ab = mm & 1;
            int rem = u, i = 0;
            while (rem >= NO - i) { rem -= NO - i; ++i; }
            int j = i + rem;
            int ob = ab ? j : i;
            b1x0 = obj[ob * 4 + 0]; b1y0 = obj[ob * 4 + 1]; b1x1 = obj[ob * 4 + 2]; b1y1 = obj[ob * 4 + 3];
            g0x = sub[u * 4 + 0]; g0y = sub[u * 4 + 1]; g1x = sub[u * 4 + 2]; g1y = sub[u * 4 + 3];
            dst = &g_imap[((b * NU + u) * 2 + ab) * P2 + pq];
        }
        float bw = (g1x - g0x) * (1.f / 7.f), bh = (g1y - g0y) * (1.f / 7.f);
        float gx0 = g0x + bw * (float)q, gy0 = g0y + bh * (float)p;
        float ox = fmaxf(0.f, fminf(gx0 + bw, b1x1) - fmaxf(gx0, b1x0));
        float oy = fmaxf(0.f, fminf(gy0 + bh, b1y1) - fmaxf(gy0, b1y0));
        *dst = oy * ox / fmaxf(bw * bh, 1e-8f);
    }
}

// ---------------- channel-last pooling, FFMA2 (stable 220us form) --------------
__global__ __launch_bounds__(256, 3) void k_poolT(const float* __restrict__ boxes,
                                                  int mode, int rois_per_img,
                                                  const float* __restrict__ bof) {
    int roi = blockIdx.x;
    int cg = blockIdx.y;
    int img = roi / rois_per_img;
    const float* bp = (mode == 1) ? (boxes + roi * 4) : (g_ub + roi * 4);
    float bx0 = bp[0], by0 = bp[1], bx1 = bp[2], by1 = bp[3];
    const float s16 = 0.0625f;
    float lox = bx0 * s16, hix = bx1 * s16, loy = by0 * s16, hiy = by1 * s16;
    float bwx = (hix - lox) * (1.f / 7.f), bwy = (hiy - loy) * (1.f / 7.f);
    float inv_area = 1.f / fmaxf(bwx * bwy, 1e-8f);

    __shared__ float wx7[32][8];
    __shared__ float wy7[32][8];
    int tid = threadIdx.x;
    if (tid < 64) {
        int w = tid & 31;
        bool isy = tid >= 32;
        float lo = isy ? loy : lox;
        float bwv = isy ? bwy : bwx;
        float* dst = isy ? &wy7[w][0] : &wx7[w][0];
#pragma unroll
        for (int q = 0; q < 7; ++q) {
            float s = lo + bwv * (float)q;
            dst[q] = hat_int(s + bwv - (float)w) - hat_int(s - (float)w);
        }
        dst[7] = 0.f;
    }
    __syncthreads();

    int hmin = max(0, (int)ceilf(loy - 1.f));
    int hmax = min(31, (int)floorf(hiy + 1.f));
    int wmin = max(0, (int)ceilf(lox - 1.f));
    int wmax = min(31, (int)floorf(hix + 1.f));

    int ch_off = (mode == 2) ? (256 + cg * 256) : 0;
    const float* Fp = g_Ft + (size_t)img * HWP * FCH + ch_off + tid;

    u64 acc2[7][4];
#pragma unroll
    for (int p = 0; p < 7; ++p)
#pragma unroll
        for (int k = 0; k < 4; ++k) acc2[p][k] = 0ull;

    for (int h = hmin; h <= hmax; ++h) {
        u64 tq2[4] = {0ull, 0ull, 0ull, 0ull};
        const float* Fh = Fp + (size_t)(h * 32) * FCH;
        for (int w = wmin; w <= wmax; ++w) {
            float f = Fh[(size_t)w * FCH];
            u64 ff = pk2(f, f);
            ulonglong2 wa = *(const ulonglong2*)&wx7[w][0];
            ulonglong2 wb = *(const ulonglong2*)&wx7[w][4];
            tq2[0] = fma2(ff, wa.x, tq2[0]);
            tq2[1] = fma2(ff, wa.y, tq2[1]);
            tq2[2] = fma2(ff, wb.x, tq2[2]);
            tq2[3] = fma2(ff, wb.y, tq2[3]);
        }
#pragma unroll
        for (int p = 0; p < 7; ++p) {
            float wyv = wy7[h][p];
            u64 wyp = pk2(wyv, wyv);
#pragma unroll
            for (int k = 0; k < 4; ++k) acc2[p][k] = fma2(wyp, tq2[k], acc2[p][k]);
        }
    }

    if (mode == 2) {
        __half* o = g_Puh + (size_t)roi * P2 * 768 + cg * 256 + tid;
#pragma unroll
        for (int p = 0; p < 7; ++p) {
            float aq[8];
#pragma unroll
            for (int k = 0; k < 4; ++k) upk2(acc2[p][k], aq[2 * k], aq[2 * k + 1]);
#pragma unroll
            for (int q = 0; q < 7; ++q)
                o[(size_t)(p * 7 + q) * 768] = __float2half(aq[q] * inv_area);
        }
    } else {
        const float* K = g_KL + ((size_t)(img * 2 + 0) * P2) * DD + tid;
        const float* L = g_KL + ((size_t)(img * 2 + 1) * P2) * DD + tid;
        const float* bm = g_bimap + (size_t)roi * P2;
        float bv = bof[tid];
        float* o = g_objf + (size_t)roi * P2 * DD + tid;
#pragma unroll
        for (int p = 0; p < 7; ++p) {
            float aq[8];
#pragma unroll
            for (int k = 0; k < 4; ++k) upk2(acc2[p][k], aq[2 * k], aq[2 * k + 1]);
#pragma unroll
            for (int q = 0; q < 7; ++q) {
                int pq = p * 7 + q;
                o[(size_t)pq * DD] = aq[q] * inv_area + K[(size_t)pq * DD]
                                   + L[(size_t)pq * DD] * bm[pq] + bv;
            }
        }
    }
}

// ---------------- mode-0 pool: raw input full-image box -> g_I0 ----------------
__global__ void k_pool0(const float* __restrict__ src) {
    int img = blockIdx.x;
    int c0 = blockIdx.y * 32;
    float lox = 0.f, loy = 0.f;
    float bwx = 32.f / 7.f, bwy = 32.f / 7.f;
    __shared__ float sWx[224], sWy[224], tile[2][32 * 33];
    int tid = threadIdx.x;
    {
        int p = tid >> 5, i = tid & 31;
        float sx = lox + bwx * (float)p;
        sWx[tid] = hat_int(sx + bwx - (float)i) - hat_int(sx - (float)i);
        float sy = loy + bwy * (float)p;
        sWy[tid] = hat_int(sy + bwy - (float)i) - hat_int(sy - (float)i);
    }
    const float* Fp = src + (size_t)img * CCH * HWP + (size_t)c0 * HWP;
    for (int e = tid; e < 1024; e += 224) {
        int cc = e >> 5, w = e & 31;
        tile[0][cc * 33 + w] = Fp[(size_t)cc * HWP + w];
    }
    int c = tid & 31, q = tid >> 5;
    float acc[7] = {};
    for (int h = 0; h < 32; ++h) {
        __syncthreads();
        if (h < 31) {
            int hb = (h + 1) & 1;
            for (int e = tid; e < 1024; e += 224) {
                int cc = e >> 5, w = e & 31;
                tile[hb][cc * 33 + w] = Fp[(size_t)cc * HWP + (h + 1) * 32 + w];
            }
        }
        float t = 0.f;
        const float* wx = &sWx[q * 32];
        const float* tr = &tile[h & 1][c * 33];
        for (int w = 0; w < 32; ++w) t += tr[w] * wx[w];
#pragma unroll
        for (int p = 0; p < 7; ++p) acc[p] += t * sWy[p * 32 + h];
    }
    int d = c0 + c;
    float* o = g_I0 + ((size_t)img * CCH + d) * P2;
#pragma unroll
    for (int p = 0; p < 7; ++p) o[p * 7 + q] = acc[p];
}

// ---------------- K2b: ctx_pool --------------------------------------------------
__global__ void k_ctx(const float* __restrict__ Wc, const float* __restrict__ bc) {
    int b = blockIdx.x, pq = blockIdx.y;
    int c = threadIdx.x;
    __shared__ float S;
    if (c == 0) {
        int p = pq / 7, q = pq - p * 7;
        float bw = 32.f / 7.f;
        float sx = 0.f, sy = 0.f;
        float st = bw * q, en = st + bw;
        for (int i = 0; i < 32; ++i) sx += hat_int(en - (float)i) - hat_int(st - (float)i);
        st = bw * p; en = st + bw;
        for (int i = 0; i < 32; ++i) sy += hat_int(en - (float)i) - hat_int(st - (float)i);
        S = sx * sy;
    }
    __syncthreads();
    float acc = 0.f;
    const float* I = g_I0 + (size_t)b * CCH * P2 + pq;
    const float* w = Wc + c * CCH;
    for (int k = 0; k < CCH; ++k) acc += w[k] * I[k * P2];
    const float inv_area = (7.f * 7.f) / (32.f * 32.f);
    g_ctx[((size_t)b * CCH + c) * P2 + pq] = (acc + bc[c] * S) * inv_area;
}

// ---------------- K2c: K/L images, layout [img][s][pq][d] ----------------------
__global__ void k_KL(const float* __restrict__ Wof) {
    int b = blockIdx.x, s = blockIdx.y, pq = blockIdx.z;
    int d = threadIdx.x;
    float acc = 0.f;
    const float* w = Wof + d * 512 + 256 + s * 128;
    const float* x = g_ctx + ((size_t)b * CCH + s * 128) * P2 + pq;
    for (int k = 0; k < 128; ++k) acc += w[k] * x[k * P2];
    g_KL[((size_t)(b * 2 + s) * P2 + pq) * DD + d] = acc;
}

// ---------------- K6: A_sub/A_obj (fp16 out), layouts [roi][pq][d] -------------
__global__ void k_A(const float* __restrict__ Wrf) {
    int bi = blockIdx.x;
    int s = blockIdx.y;
    int d = threadIdx.x;
    __shared__ float Xs[64 * 49];   // [kl][pq]
    const float* X = g_objf + (size_t)bi * P2 * DD;   // [pq][k]
    const float* w = Wrf + d * 896 + s * 256;
    float acc[P2];
#pragma unroll
    for (int pq = 0; pq < P2; ++pq) acc[pq] = 0.f;
    for (int k0 = 0; k0 < 256; k0 += 64) {
        __syncthreads();
        for (int e = d; e < 64 * 49; e += 256) {
            int pq = e >> 6, kl = e & 63;
            Xs[kl * 49 + pq] = X[pq * 256 + k0 + kl];
        }
        __syncthreads();
        for (int kl = 0; kl < 64; ++kl) {
            float wv = w[k0 + kl];
            const float* xr = &Xs[kl * 49];
#pragma unroll
            for (int pq = 0; pq < P2; ++pq) acc[pq] += wv * xr[pq];
        }
    }
    __half* o = g_Ah + (((size_t)bi * 2 + s) * P2) * DD + d;
#pragma unroll
    for (int pq = 0; pq < P2; ++pq) o[(size_t)pq * DD] = __float2half(acc[pq]);
}

// ---------------- K7: pair assembly + relu, __half2 d-pairs, 128 threads --------
__global__ void k_pair(const float* __restrict__ brf) {
    int bu = blockIdx.x;            // b*NU + u
    int b = bu / NU, u = bu - b * NU;
    int rem = u, i = 0;
    while (rem >= NO - i) { rem -= NO - i; ++i; }
    int j = i + rem;                // i <= j
    __shared__ float imA[P2], imB[P2];
    int tid = threadIdx.x;          // 0..127, owns d = 2*tid, 2*tid+1
    if (tid < P2) {
        imA[tid] = g_imap[((size_t)bu * 2 + 0) * P2 + tid];
        imB[tid] = g_imap[((size_t)bu * 2 + 1) * P2 + tid];
    }
    __syncthreads();
    const __half2* Ai_s = (const __half2*)(g_Ah + ((size_t)(b * NO + i) * 2 + 0) * P2 * DD) + tid;
    const __half2* Ai_o = (const __half2*)(g_Ah + ((size_t)(b * NO + i) * 2 + 1) * P2 * DD) + tid;
    const __half2* Aj_s = (const __half2*)(g_Ah + ((size_t)(b * NO + j) * 2 + 0) * P2 * DD) + tid;
    const __half2* Aj_o = (const __half2*)(g_Ah + ((size_t)(b * NO + j) * 2 + 1) * P2 * DD) + tid;
    const __half2* Pu = (const __half2*)(g_Puh + (size_t)bu * P2 * 768) + tid;
    __half2* X0 = (__half2*)(g_Xh + (size_t)(b * NPAIR + i * NO + j) * KFC) + tid;
    __half2* X1 = (__half2*)(g_Xh + (size_t)(b * NPAIR + j * NO + i) * KFC) + tid;
    float2 bv = *(const float2*)&brf[tid * 2];
    bool diag = (i == j);
#pragma unroll 1
    for (int pq = 0; pq < P2; ++pq) {
        float ia = imA[pq], ib = imB[pq];
        float2 x = __half22float2(Pu[pq * 384]);
        float2 y = __half22float2(Pu[pq * 384 + 128]);
        float2 z = __half22float2(Pu[pq * 384 + 256]);
        float2 as0 = __half22float2(Ai_s[pq * 128]);
        float2 ao1 = __half22float2(Aj_o[pq * 128]);
        float v0x = as0.x + ao1.x + x.x + ia * y.x + ib * z.x + bv.x;
        float v0y = as0.y + ao1.y + x.y + ia * y.y + ib * z.y + bv.y;
        X0[pq * 128] = __floats2half2_rn(fmaxf(v0x, 0.f), fmaxf(v0y, 0.f));
        if (!diag) {
            float2 as1 = __half22float2(Aj_s[pq * 128]);
            float2 ao0 = __half22float2(Ai_o[pq * 128]);
            float v1x = as1.x + ao0.x + x.x + ib * y.x + ia * z.x + bv.x;
            float v1y = as1.y + ao0.y + x.y + ib * y.y + ia * z.y + bv.y;
            X1[pq * 128] = __floats2half2_rn(fmaxf(v1x, 0.f), fmaxf(v1y, 0.f));
        }
    }
}

// ---------------- weight permutations --------------------------------------------
__global__ void k_permWh(const float* __restrict__ W, __half* __restrict__ dst) {
    __shared__ float s[64 * 49];
    int dg = blockIdx.x;
    int n = blockIdx.y;
    int tid = threadIdx.x;
    const float* src = W + (size_t)n * KFC + dg * 64 * 49;
    for (int e = tid; e < 64 * 49; e += 256) s[e] = src[e];
    __syncthreads();
    __half* o = dst + (size_t)n * KFC + dg * 64;
    for (int e = tid; e < 64 * 49; e += 256) {
        int pq = e >> 6, dl = e & 63;
        o[(size_t)pq * 256 + dl] = __float2half(s[dl * 49 + pq]);
    }
}
__global__ void k_permW(const float* __restrict__ W, float* __restrict__ dst) {
    __shared__ float s[64 * 49];
    int dg = blockIdx.x;
    int n = blockIdx.y;
    int tid = threadIdx.x;
    const float* src = W + (size_t)n * KFC + dg * 64 * 49;
    for (int e = tid; e < 64 * 49; e += 256) s[e] = src[e];
    __syncthreads();
    float* o = dst + (size_t)n * KFC + dg * 64;
    for (int e = tid; e < 64 * 49; e += 256) {
        int pq = e >> 6, dl = e & 63;
        o[(size_t)pq * 256 + dl] = s[dl * 49 + pq];
    }
}

// ---------------- rel FC: TF32 MMA, A and B read from fp16, split-K ------------
__global__ __launch_bounds__(256) void k_fc_tf32(int M, int kchunk) {
    __shared__ unsigned As[16][136];
    __shared__ unsigned Bs[16][136];
    int m0 = blockIdx.x * 128, n0 = blockIdx.y * 128, z = blockIdx.z;
    int kb = z * kchunk;
    int tid = threadIdx.x;
    int row = tid >> 1, kq = (tid & 1) * 8;
    const __half* Ap = g_Xh + (size_t)(m0 + row) * KFC + kb + kq;
    const __half* Bp = g_Wph + (size_t)(n0 + row) * KFC + kb + kq;
    int lane = tid & 31;
    int g = lane >> 2, tg = lane & 3;
    int warp = tid >> 5;
    int wm = (warp & 3) * 32, wn = (warp >> 2) * 64;

    float acc[2][8][4];
#pragma unroll
    for (int mi = 0; mi < 2; ++mi)
#pragma unroll
        for (int nj = 0; nj < 8; ++nj)
#pragma unroll
            for (int r = 0; r < 4; ++r) acc[mi][nj][r] = 0.f;

    uint4 rah = *(const uint4*)(Ap);
    uint4 rbh = *(const uint4*)(Bp);

    for (int k0 = 0; k0 < kchunk; k0 += 16) {
        {
            float2 f0 = __half22float2(*(__half2*)&rah.x), f1 = __half22float2(*(__half2*)&rah.y);
            float2 f2 = __half22float2(*(__half2*)&rah.z), f3 = __half22float2(*(__half2*)&rah.w);
            As[kq + 0][row] = f2tf32(f0.x); As[kq + 1][row] = f2tf32(f0.y);
            As[kq + 2][row] = f2tf32(f1.x); As[kq + 3][row] = f2tf32(f1.y);
            As[kq + 4][row] = f2tf32(f2.x); As[kq + 5][row] = f2tf32(f2.y);
            As[kq + 6][row] = f2tf32(f3.x); As[kq + 7][row] = f2tf32(f3.y);
        }
        {
            float2 f0 = __half22float2(*(__half2*)&rbh.x), f1 = __half22float2(*(__half2*)&rbh.y);
            float2 f2 = __half22float2(*(__half2*)&rbh.z), f3 = __half22float2(*(__half2*)&rbh.w);
            Bs[kq + 0][row] = f2tf32(f0.x); Bs[kq + 1][row] = f2tf32(f0.y);
            Bs[kq + 2][row] = f2tf32(f1.x); Bs[kq + 3][row] = f2tf32(f1.y);
            Bs[kq + 4][row] = f2tf32(f2.x); Bs[kq + 5][row] = f2tf32(f2.y);
            Bs[kq + 6][row] = f2tf32(f3.x); Bs[kq + 7][row] = f2tf32(f3.y);
        }
        __syncthreads();
        int kn = k0 + 16;
        if (kn < kchunk) {
            rah = *(const uint4*)(Ap + kn);
            rbh = *(const uint4*)(Bp + kn);
        }
#pragma unroll
        for (int kk = 0; kk < 16; kk += 8) {
            unsigned af[2][4];
#pragma unroll
            for (int mi = 0; mi < 2; ++mi) {
                int mb = wm + mi * 16;
                af[mi][0] = As[kk + tg][mb + g];
                af[mi][1] = As[kk + tg][mb + g + 8];
                af[mi][2] = As[kk + tg + 4][mb + g];
                af[mi][3] = As[kk + tg + 4][mb + g + 8];
            }
            unsigned bf[8][2];
#pragma unroll
            for (int nj = 0; nj < 8; ++nj) {
                bf[nj][0] = Bs[kk + tg][wn + nj * 8 + g];
                bf[nj][1] = Bs[kk + tg + 4][wn + nj * 8 + g];
            }
#pragma unroll
            for (int mi = 0; mi < 2; ++mi)
#pragma unroll
                for (int nj = 0; nj < 8; ++nj) {
                    asm volatile(
                        "mma.sync.aligned.m16n8k8.row.col.f32.tf32.tf32.f32 "
                        "{%0,%1,%2,%3},{%4,%5,%6,%7},{%8,%9},{%0,%1,%2,%3};"
                        : "+f"(acc[mi][nj][0]), "+f"(acc[mi][nj][1]),
                          "+f"(acc[mi][nj][2]), "+f"(acc[mi][nj][3])
                        : "r"(af[mi][0]), "r"(af[mi][1]), "r"(af[mi][2]), "r"(af[mi][3]),
                          "r"(bf[nj][0]), "r"(bf[nj][1]));
                }
        }
        __syncthreads();
    }
#pragma unroll
    for (int mi = 0; mi < 2; ++mi) {
        int m = m0 + wm + mi * 16 + g;
#pragma unroll
        for (int nj = 0; nj < 8; ++nj) {
            int n = n0 + wn + nj * 8 + 2 * tg;
            float* p0 = &g_part[((size_t)z * M + m) * 256 + n];
            float* p1 = &g_part[((size_t)z * M + m + 8) * 256 + n];
            *(float2*)p0 = make_float2(acc[mi][nj][0], acc[mi][nj][1]);
            *(float2*)p1 = make_float2(acc[mi][nj][2], acc[mi][nj][3]);
        }
    }
}

// ---------------- obj FC: fp32 SIMT, split-K, relu at load ----------------------
__global__ __launch_bounds__(256) void k_fc2(const float* __restrict__ W,
                                             int M, int kchunk) {
    __shared__ float As[16][128];
    __shared__ float Bs[16][128];
    const float* A = (const float*)g_objf;
    int m0 = blockIdx.x * 128, n0 = blockIdx.y * 128, z = blockIdx.z;
    int kb = z * kchunk;
    int tid = threadIdx.x;
    int tx = tid & 15, ty = tid >> 4;
    int arow = tid >> 1, akq = (tid & 1) * 8;
    const float* Ap = A + (size_t)(m0 + arow) * KFC + kb;
    const float* Bp = W + (size_t)(n0 + arow) * KFC + kb;
    float4 ra0 = *(const float4*)(Ap + akq);
    float4 ra1 = *(const float4*)(Ap + akq + 4);
    float4 rb0 = *(const float4*)(Bp + akq);
    float4 rb1 = *(const float4*)(Bp + akq + 4);
    float acc[8][8] = {};
    for (int k0 = 0; k0 < kchunk; k0 += 16) {
        ra0.x = fmaxf(ra0.x, 0.f); ra0.y = fmaxf(ra0.y, 0.f);
        ra0.z = fmaxf(ra0.z, 0.f); ra0.w = fmaxf(ra0.w, 0.f);
        ra1.x = fmaxf(ra1.x, 0.f); ra1.y = fmaxf(ra1.y, 0.f);
        ra1.z = fmaxf(ra1.z, 0.f); ra1.w = fmaxf(ra1.w, 0.f);
        As[akq + 0][arow] = ra0.x; As[akq + 1][arow] = ra0.y;
        As[akq + 2][arow] = ra0.z; As[akq + 3][arow] = ra0.w;
        As[akq + 4][arow] = ra1.x; As[akq + 5][arow] = ra1.y;
        As[akq + 6][arow] = ra1.z; As[akq + 7][arow] = ra1.w;
        Bs[akq + 0][arow] = rb0.x; Bs[akq + 1][arow] = rb0.y;
        Bs[akq + 2][arow] = rb0.z; Bs[akq + 3][arow] = rb0.w;
        Bs[akq + 4][arow] = rb1.x; Bs[akq + 5][arow] = rb1.y;
        Bs[akq + 6][arow] = rb1.z; Bs[akq + 7][arow] = rb1.w;
        __syncthreads();
        int kn = k0 + 16;
        if (kn < kchunk) {
            ra0 = *(const float4*)(Ap + kn + akq);
            ra1 = *(const float4*)(Ap + kn + akq + 4);
            rb0 = *(const float4*)(Bp + kn + akq);
            rb1 = *(const float4*)(Bp + kn + akq + 4);
        }
#pragma unroll
        for (int kk = 0; kk < 16; ++kk) {
            float4 a0 = *(const float4*)&As[kk][ty * 8];
            float4 a1 = *(const float4*)&As[kk][ty * 8 + 4];
            float4 b0 = *(const float4*)&Bs[kk][tx * 8];
            float4 b1 = *(const float4*)&Bs[kk][tx * 8 + 4];
            float av[8] = {a0.x, a0.y, a0.z, a0.w, a1.x, a1.y, a1.z, a1.w};
            float bv[8] = {b0.x, b0.y, b0.z, b0.w, b1.x, b1.y, b1.z, b1.w};
#pragma unroll
            for (int i = 0; i < 8; ++i)
#pragma unroll
                for (int j = 0; j < 8; ++j) acc[i][j] += av[i] * bv[j];
        }
        __syncthreads();
    }
#pragma unroll
    for (int i = 0; i < 8; ++i) {
        int m = m0 + ty * 8 + i;
        float* o = &g_part[((size_t)z * M + m) * 256 + n0 + tx * 8];
        *(float4*)o       = make_float4(acc[i][0], acc[i][1], acc[i][2], acc[i][3]);
        *(float4*)(o + 4) = make_float4(acc[i][4], acc[i][5], acc[i][6], acc[i][7]);
    }
}

// reduce split-K partials + bias
__global__ void k_reduce(int which, const float* __restrict__ bias, int M, int Z) {
    int idx = blockIdx.x * 256 + threadIdx.x;
    if (idx >= M * 256) return;
    float s = bias[idx & 255];
    for (int z = 0; z < Z; ++z) s += g_part[(size_t)z * M * 256 + idx];
    if (which) g_O[idx] = s; else g_R[idx] = s;
}

// ---------------- K10: L2 normalize ---------------------------------------------
__global__ void k_norm(float* __restrict__ dst, int which) {
    int r = blockIdx.x, tid = threadIdx.x;
    const float* src = which ? (const float*)g_R : (const float*)g_O;
    float v = src[(size_t)r * DD + tid];
    float s = v * v;
#pragma unroll
    for (int o = 16; o > 0; o >>= 1) s += __shfl_xor_sync(0xffffffffu, s, o);
    __shared__ float ws[8];
    if ((tid & 31) == 0) ws[tid >> 5] = s;
    __syncthreads();
    float tot = 0.f;
#pragma unroll
    for (int k = 0; k < 8; ++k) tot += ws[k];
    dst[(size_t)r * DD + tid] = v * rsqrtf(tot);
}

// ---------------- launch ----------------------------------------------------------
extern "C" void kernel_launch(void* const* d_in, const int* in_sizes, int n_in,
                              void* d_out, int out_size) {
    const float* input   = (const float*)d_in[0];
    const float* objects = (const float*)d_in[1];
    const float* Wc   = (const float*)d_in[3];
    const float* bc   = (const float*)d_in[4];
    const float* Wr   = (const float*)d_in[5];
    const float* br   = (const float*)d_in[6];
    const float* Wof  = (const float*)d_in[7];
    const float* bof  = (const float*)d_in[8];
    const float* Wrf  = (const float*)d_in[9];
    const float* brf  = (const float*)d_in[10];
    const float* Wofc = (const float*)d_in[11];
    const float* bofc = (const float*)d_in[12];
    const float* Wrfc = (const float*)d_in[13];
    const float* brfc = (const float*)d_in[14];
    float* out = (float*)d_out;

    __half* wph; cudaGetSymbolAddress((void**)&wph, g_Wph);
    float* wp2;  cudaGetSymbolAddress((void**)&wp2, g_Wp2);

    k_combine<<<1024, 256>>>(Wof, Wrf, Wr, br);
    k_geom<<<8, 256>>>(objects);
    k_pool0<<<dim3(8, 8), 224>>>(input);                                 // I0 raw
    k_projT_mma<<<dim3(8, 8, 8), 256>>>(input);                          // <-- profiled (TF32 MMA)
    k_poolT<<<dim3(1088, 3), 256>>>(nullptr, 2, NU, nullptr);            // union pool
    k_ctx<<<dim3(8, 49), 256>>>(Wc, bc);
    k_KL<<<dim3(8, 2, 49), 256>>>(Wof);
    k_poolT<<<dim3(128, 1), 256>>>(objects, 1, NO, bof);                 // obj pool + epi
    k_A<<<dim3(128, 2), 256>>>(Wrf);
    k_pair<<<1088, 128>>>(brf);
    k_permWh<<<dim3(4, 256), 256>>>(Wrfc, wph);
    k_fc_tf32<<<dim3(16, 2, 8), 256>>>(2048, 1568);                      // rel FC (TF32, fp16 A+B)
    k_reduce<<<2048, 256>>>(0, brfc, 2048, 8);
    k_permW<<<dim3(4, 256), 256>>>(Wofc, wp2);
    k_fc2<<<dim3(1, 2, 16), 256>>>(wp2, 128, 784);                       // obj FC
    k_reduce<<<128, 256>>>(1, bofc, 128, 16);
    k_norm<<<128, 256>>>(out, 0);                                        // obj_out
    k_norm<<<2048, 256>>>(out + 32768, 1);                               // rel_out
    (void)in_sizes; (void)n_in; (void)out_size;
}

// round 17
// speedup vs baseline: 1.1671x; 1.0227x over previous
#include <cuda_runtime.h>
#include <cuda_fp16.h>

// ---------------- problem constants ----------------
#define BB    8
#define CCH   256
#define HWP   1024
#define NO    16
#define NPAIR 256
#define NU    136
#define P2    49
#define DD    256
#define KFC   12544
#define FCH   1024

typedef unsigned long long u64;

// ---------------- scratch ----------------
__device__ float g_M[FCH * CCH];
__device__ float g_cb[FCH];
__device__ float g_Ft[BB * HWP * FCH];                 // channel-last projected features
__device__ float g_I0[BB * CCH * P2];
__device__ float g_ctx[BB * CCH * P2];
__device__ float g_KL[BB * 2 * P2 * DD];               // [img][s][pq][d]
__device__ float g_ub[BB * NU * 4];
__device__ float g_imap[BB * NU * 2 * P2];
__device__ float g_bimap[BB * NO * P2];
__device__ float g_objf[BB * NO * P2 * DD];            // [roi][pq][d]
__device__ __half g_Ah[BB * NO * 2 * P2 * DD];         // A_sub/A_obj, fp16
__device__ __half g_Puh[BB * NU * P2 * 768];           // pooled rel, fp16
__device__ __half g_Xh[(size_t)BB * NPAIR * KFC];      // relu(rel_feat), fp16
__device__ __half g_Wph[DD * KFC];                     // Wrfc permuted, fp16
__device__ float g_Wp2[DD * KFC];                      // Wofc permuted, fp32
__device__ float g_part[8 * 2048 * 256];
__device__ float g_R[BB * NPAIR * DD];
__device__ float g_O[BB * NO * DD];

__device__ __forceinline__ float hat_int(float t) {
    t = fminf(1.f, fmaxf(-1.f, t));
    return (t < 0.f) ? 0.5f * (t + 1.f) * (t + 1.f) : 1.f - 0.5f * (1.f - t) * (1.f - t);
}

__device__ __forceinline__ unsigned f2tf32(float x) {
    unsigned r;
    asm("cvt.rna.tf32.f32 %0, %1;" : "=r"(r) : "f"(x));
    return r;
}

// ---- packed f32x2 helpers ----
__device__ __forceinline__ u64 pk2(float lo, float hi) {
    u64 r;
    asm("mov.b64 %0, {%1, %2};" : "=l"(r) : "f"(lo), "f"(hi));
    return r;
}
__device__ __forceinline__ u64 fma2(u64 a, u64 b, u64 c) {
    u64 d;
    asm("fma.rn.f32x2 %0, %1, %2, %3;" : "=l"(d) : "l"(a), "l"(b), "l"(c));
    return d;
}
__device__ __forceinline__ void upk2(u64 v, float& lo, float& hi) {
    asm("mov.b64 {%0, %1}, %2;" : "=f"(lo), "=f"(hi) : "l"(v));
}

// ---------------- K0: combine weights ------------------------------------------
__global__ void k_combine(const float* __restrict__ Wof, const float* __restrict__ Wrf,
                          const float* __restrict__ Wr, const float* __restrict__ br) {
    int row = blockIdx.x;
    int c = threadIdx.x;
    if (row < 256) {
        g_M[row * CCH + c] = Wof[row * 512 + c];
        if (c == 0) g_cb[row] = 0.f;
    } else {
        int s = (row - 256) >> 8;
        int d = (row - 256) & 255;
        const float* w = Wrf + d * 896 + 512 + s * 128;
        float acc = 0.f;
        for (int k = 0; k < 128; ++k) acc += w[k] * Wr[(s * 128 + k) * CCH + c];
        g_M[row * CCH + c] = acc;
        if (c == 0) {
            float cb = 0.f;
            for (int k = 0; k < 128; ++k) cb += w[k] * br[s * 128 + k];
            g_cb[row] = cb;
        }
    }
}

// ---------------- K1: projection GEMM, TF32 MMA, output g_Ft[n][m] -------------
__global__ __launch_bounds__(256) void k_projT_mma(const float* __restrict__ input) {
    __shared__ unsigned As[16][136];   // [k][n]
    __shared__ unsigned Bs[16][136];   // [k][m]
    int b = blockIdx.z;
    const float* In = input + (size_t)b * CCH * HWP;
    float* C = g_Ft + (size_t)b * HWP * FCH;
    int nt0 = blockIdx.x * 128, mt0 = blockIdx.y * 128;
    int tid = threadIdx.x;
    int krow = tid >> 4, ncol = (tid & 15) * 8;
    int mrow = tid >> 1, kq = (tid & 1) * 8;
    const float* Apt = In + nt0 + ncol;
    const float* Bpt = g_M + (size_t)(mt0 + mrow) * CCH;
    int lane = tid & 31;
    int g = lane >> 2, tg = lane & 3;
    int warp = tid >> 5;
    int wm = (warp & 3) * 32;
    int wn = (warp >> 2) * 64;

    float acc[2][8][4];
#pragma unroll
    for (int mi = 0; mi < 2; ++mi)
#pragma unroll
        for (int nj = 0; nj < 8; ++nj)
#pragma unroll
            for (int r = 0; r < 4; ++r) acc[mi][nj][r] = 0.f;

    float4 ra0 = *(const float4*)(Apt + (size_t)krow * HWP);
    float4 ra1 = *(const float4*)(Apt + (size_t)krow * HWP + 4);
    float4 rb0 = *(const float4*)(Bpt + kq);
    float4 rb1 = *(const float4*)(Bpt + kq + 4);

    for (int k0 = 0; k0 < CCH; k0 += 16) {
        {
            uint4 v0 = make_uint4(f2tf32(ra0.x), f2tf32(ra0.y), f2tf32(ra0.z), f2tf32(ra0.w));
            uint4 v1 = make_uint4(f2tf32(ra1.x), f2tf32(ra1.y), f2tf32(ra1.z), f2tf32(ra1.w));
            *(uint4*)&As[krow][ncol] = v0;
            *(uint4*)&As[krow][ncol + 4] = v1;
        }
        Bs[kq + 0][mrow] = f2tf32(rb0.x); Bs[kq + 1][mrow] = f2tf32(rb0.y);
        Bs[kq + 2][mrow] = f2tf32(rb0.z); Bs[kq + 3][mrow] = f2tf32(rb0.w);
        Bs[kq + 4][mrow] = f2tf32(rb1.x); Bs[kq + 5][mrow] = f2tf32(rb1.y);
        Bs[kq + 6][mrow] = f2tf32(rb1.z); Bs[kq + 7][mrow] = f2tf32(rb1.w);
        __syncthreads();
        int kn = k0 + 16;
        if (kn < CCH) {
            ra0 = *(const float4*)(Apt + (size_t)(kn + krow) * HWP);
            ra1 = *(const float4*)(Apt + (size_t)(kn + krow) * HWP + 4);
            rb0 = *(const float4*)(Bpt + kn + kq);
            rb1 = *(const float4*)(Bpt + kn + kq + 4);
        }
#pragma unroll
        for (int kk = 0; kk < 16; kk += 8) {
            unsigned af[2][4];
#pragma unroll
            for (int mi = 0; mi < 2; ++mi) {
                int nb = wm + mi * 16;
                af[mi][0] = As[kk + tg][nb + g];
                af[mi][1] = As[kk + tg][nb + g + 8];
                af[mi][2] = As[kk + tg + 4][nb + g];
                af[mi][3] = As[kk + tg + 4][nb + g + 8];
            }
            unsigned bf[8][2];
#pragma unroll
            for (int nj = 0; nj < 8; ++nj) {
                bf[nj][0] = Bs[kk + tg][wn + nj * 8 + g];
                bf[nj][1] = Bs[kk + tg + 4][wn + nj * 8 + g];
            }
#pragma unroll
            for (int mi = 0; mi < 2; ++mi)
#pragma unroll
                for (int nj = 0; nj < 8; ++nj) {
                    asm volatile(
                        "mma.sync.aligned.m16n8k8.row.col.f32.tf32.tf32.f32 "
                        "{%0,%1,%2,%3},{%4,%5,%6,%7},{%8,%9},{%0,%1,%2,%3};"
                        : "+f"(acc[mi][nj][0]), "+f"(acc[mi][nj][1]),
                          "+f"(acc[mi][nj][2]), "+f"(acc[mi][nj][3])
                        : "r"(af[mi][0]), "r"(af[mi][1]), "r"(af[mi][2]), "r"(af[mi][3]),
                          "r"(bf[nj][0]), "r"(bf[nj][1]));
                }
        }
        __syncthreads();
    }
#pragma unroll
    for (int mi = 0; mi < 2; ++mi) {
        int n = nt0 + wm + mi * 16 + g;
#pragma unroll
        for (int nj = 0; nj < 8; ++nj) {
            int m = mt0 + wn + nj * 8 + 2 * tg;
            float2 cb = *(const float2*)&g_cb[m];
            float* p0 = &C[(size_t)n * FCH + m];
            float* p1 = &C[(size_t)(n + 8) * FCH + m];
            *(float2*)p0 = make_float2(acc[mi][nj][0] + cb.x, acc[mi][nj][1] + cb.y);
            *(float2*)p1 = make_float2(acc[mi][nj][2] + cb.x, acc[mi][nj][3] + cb.y);
        }
    }
}

// ---------------- K3: geometry ---------------------------------------------------
__global__ void k_geom(const float* __restrict__ objects) {
    int b = blockIdx.x;
    int tid = threadIdx.x;
    const float* obj = objects + b * NO * 4;
    __shared__ float sub[NU * 4];
    if (tid < NU) {
        int rem = tid, i = 0;
        while (rem >= NO - i) { rem -= NO - i; ++i; }
        int j = i + rem;
        float x0 = fminf(obj[i * 4 + 0], obj[j * 4 + 0]);
        float y0 = fminf(obj[i * 4 + 1], obj[j * 4 + 1]);
        float x1 = fmaxf(obj[i * 4 + 2], obj[j * 4 + 2]);
        float y1 = fmaxf(obj[i * 4 + 3], obj[j * 4 + 3]);
        sub[tid * 4 + 0] = x0; sub[tid * 4 + 1] = y0; sub[tid * 4 + 2] = x1; sub[tid * 4 + 3] = y1;
        float* gu = g_ub + (b * NU + tid) * 4;
        gu[0] = x0; gu[1] = y0; gu[2] = x1; gu[3] = y1;
    }
    __syncthreads();
    int total = (NO + NU * 2) * P2;
    for (int v = tid; v < total; v += blockDim.x) {
        int m = v / P2, pq = v - (v / P2) * P2;
        int p = pq / 7, q = pq - p * 7;
        float b1x0, b1y0, b1x1, b1y1, g0x, g0y, g1x, g1y;
        float* dst;
        if (m < NO) {
            b1x0 = obj[m * 4 + 0]; b1y0 = obj[m * 4 + 1]; b1x1 = obj[m * 4 + 2]; b1y1 = obj[m * 4 + 3];
            g0x = 0.f; g0y = 0.f; g1x = 512.f; g1y = 512.f;
            dst = &g_bimap[(b * NO + m) * P2 + pq];
        } else {
            int mm = m - NO;
            int u = mm >> 1, ab = mm & 1;
            int rem = u, i = 0;
            while (rem >= NO - i) { rem -= NO - i; ++i; }
            int j = i + rem;
            int ob = ab ? j : i;
            b1x0 = obj[ob * 4 + 0]; b1y0 = obj[ob * 4 + 1]; b1x1 = obj[ob * 4 + 2]; b1y1 = obj[ob * 4 + 3];
            g0x = sub[u * 4 + 0]; g0y = sub[u * 4 + 1]; g1x = sub[u * 4 + 2]; g1y = sub[u * 4 + 3];
            dst = &g_imap[((b * NU + u) * 2 + ab) * P2 + pq];
        }
        float bw = (g1x - g0x) * (1.f / 7.f), bh = (g1y - g0y) * (1.f / 7.f);
        float gx0 = g0x + bw * (float)q, gy0 = g0y + bh * (float)p;
        float ox = fmaxf(0.f, fminf(gx0 + bw, b1x1) - fmaxf(gx0, b1x0));
        float oy = fmaxf(0.f, fminf(gy0 + bh, b1y1) - fmaxf(gy0, b1y0));
        *dst = oy * ox / fmaxf(bw * bh, 1e-8f);
    }
}

// ---------------- channel-last pooling, FFMA2 (stable 220us form) --------------
__global__ __launch_bounds__(256, 3) void k_poolT(const float* __restrict__ boxes,
                                                  int mode, int rois_per_img,
                                                  const float* __restrict__ bof) {
    int roi = blockIdx.x;
    int cg = blockIdx.y;
    int img = roi / rois_per_img;
    const float* bp = (mode == 1) ? (boxes + roi * 4) : (g_ub + roi * 4);
    float bx0 = bp[0], by0 = bp[1], bx1 = bp[2], by1 = bp[3];
    const float s16 = 0.0625f;
    float lox = bx0 * s16, hix = bx1 * s16, loy = by0 * s16, hiy = by1 * s16;
    float bwx = (hix - lox) * (1.f / 7.f), bwy = (hiy - loy) * (1.f / 7.f);
    float inv_area = 1.f / fmaxf(bwx * bwy, 1e-8f);

    __shared__ float wx7[32][8];
    __shared__ float wy7[32][8];
    int tid = threadIdx.x;
    if (tid < 64) {
        int w = tid & 31;
        bool isy = tid >= 32;
        float lo = isy ? loy : lox;
        float bwv = isy ? bwy : bwx;
        float* dst = isy ? &wy7[w][0] : &wx7[w][0];
#pragma unroll
        for (int q = 0; q < 7; ++q) {
            float s = lo + bwv * (float)q;
            dst[q] = hat_int(s + bwv - (float)w) - hat_int(s - (float)w);
        }
        dst[7] = 0.f;
    }
    __syncthreads();

    int hmin = max(0, (int)ceilf(loy - 1.f));
    int hmax = min(31, (int)floorf(hiy + 1.f));
    int wmin = max(0, (int)ceilf(lox - 1.f));
    int wmax = min(31, (int)floorf(hix + 1.f));

    int ch_off = (mode == 2) ? (256 + cg * 256) : 0;
    const float* Fp = g_Ft + (size_t)img * HWP * FCH + ch_off + tid;

    u64 acc2[7][4];
#pragma unroll
    for (int p = 0; p < 7; ++p)
#pragma unroll
        for (int k = 0; k < 4; ++k) acc2[p][k] = 0ull;

    for (int h = hmin; h <= hmax; ++h) {
        u64 tq2[4] = {0ull, 0ull, 0ull, 0ull};
        const float* Fh = Fp + (size_t)(h * 32) * FCH;
        for (int w = wmin; w <= wmax; ++w) {
            float f = Fh[(size_t)w * FCH];
            u64 ff = pk2(f, f);
            ulonglong2 wa = *(const ulonglong2*)&wx7[w][0];
            ulonglong2 wb = *(const ulonglong2*)&wx7[w][4];
            tq2[0] = fma2(ff, wa.x, tq2[0]);
            tq2[1] = fma2(ff, wa.y, tq2[1]);
            tq2[2] = fma2(ff, wb.x, tq2[2]);
            tq2[3] = fma2(ff, wb.y, tq2[3]);
        }
#pragma unroll
        for (int p = 0; p < 7; ++p) {
            float wyv = wy7[h][p];
            u64 wyp = pk2(wyv, wyv);
#pragma unroll
            for (int k = 0; k < 4; ++k) acc2[p][k] = fma2(wyp, tq2[k], acc2[p][k]);
        }
    }

    if (mode == 2) {
        __half* o = g_Puh + (size_t)roi * P2 * 768 + cg * 256 + tid;
#pragma unroll
        for (int p = 0; p < 7; ++p) {
            float aq[8];
#pragma unroll
            for (int k = 0; k < 4; ++k) upk2(acc2[p][k], aq[2 * k], aq[2 * k + 1]);
#pragma unroll
            for (int q = 0; q < 7; ++q)
                o[(size_t)(p * 7 + q) * 768] = __float2half(aq[q] * inv_area);
        }
    } else {
        const float* K = g_KL + ((size_t)(img * 2 + 0) * P2) * DD + tid;
        const float* L = g_KL + ((size_t)(img * 2 + 1) * P2) * DD + tid;
        const float* bm = g_bimap + (size_t)roi * P2;
        float bv = bof[tid];
        float* o = g_objf + (size_t)roi * P2 * DD + tid;
#pragma unroll
        for (int p = 0; p < 7; ++p) {
            float aq[8];
#pragma unroll
            for (int k = 0; k < 4; ++k) upk2(acc2[p][k], aq[2 * k], aq[2 * k + 1]);
#pragma unroll
            for (int q = 0; q < 7; ++q) {
                int pq = p * 7 + q;
                o[(size_t)pq * DD] = aq[q] * inv_area + K[(size_t)pq * DD]
                                   + L[(size_t)pq * DD] * bm[pq] + bv;
            }
        }
    }
}

// ---------------- mode-0 pool: raw input full-image box -> g_I0 ----------------
__global__ void k_pool0(const float* __restrict__ src) {
    int img = blockIdx.x;
    int c0 = blockIdx.y * 32;
    float lox = 0.f, loy = 0.f;
    float bwx = 32.f / 7.f, bwy = 32.f / 7.f;
    __shared__ float sWx[224], sWy[224], tile[2][32 * 33];
    int tid = threadIdx.x;
    {
        int p = tid >> 5, i = tid & 31;
        float sx = lox + bwx * (float)p;
        sWx[tid] = hat_int(sx + bwx - (float)i) - hat_int(sx - (float)i);
        float sy = loy + bwy * (float)p;
        sWy[tid] = hat_int(sy + bwy - (float)i) - hat_int(sy - (float)i);
    }
    const float* Fp = src + (size_t)img * CCH * HWP + (size_t)c0 * HWP;
    for (int e = tid; e < 1024; e += 224) {
        int cc = e >> 5, w = e & 31;
        tile[0][cc * 33 + w] = Fp[(size_t)cc * HWP + w];
    }
    int c = tid & 31, q = tid >> 5;
    float acc[7] = {};
    for (int h = 0; h < 32; ++h) {
        __syncthreads();
        if (h < 31) {
            int hb = (h + 1) & 1;
            for (int e = tid; e < 1024; e += 224) {
                int cc = e >> 5, w = e & 31;
                tile[hb][cc * 33 + w] = Fp[(size_t)cc * HWP + (h + 1) * 32 + w];
            }
        }
        float t = 0.f;
        const float* wx = &sWx[q * 32];
        const float* tr = &tile[h & 1][c * 33];
        for (int w = 0; w < 32; ++w) t += tr[w] * wx[w];
#pragma unroll
        for (int p = 0; p < 7; ++p) acc[p] += t * sWy[p * 32 + h];
    }
    int d = c0 + c;
    float* o = g_I0 + ((size_t)img * CCH + d) * P2;
#pragma unroll
    for (int p = 0; p < 7; ++p) o[p * 7 + q] = acc[p];
}

// ---------------- K2b: ctx_pool --------------------------------------------------
__global__ void k_ctx(const float* __restrict__ Wc, const float* __restrict__ bc) {
    int b = blockIdx.x, pq = blockIdx.y;
    int c = threadIdx.x;
    __shared__ float S;
    if (c == 0) {
        int p = pq / 7, q = pq - p * 7;
        float bw = 32.f / 7.f;
        float sx = 0.f, sy = 0.f;
        float st = bw * q, en = st + bw;
        for (int i = 0; i < 32; ++i) sx += hat_int(en - (float)i) - hat_int(st - (float)i);
        st = bw * p; en = st + bw;
        for (int i = 0; i < 32; ++i) sy += hat_int(en - (float)i) - hat_int(st - (float)i);
        S = sx * sy;
    }
    __syncthreads();
    float acc = 0.f;
    const float* I = g_I0 + (size_t)b * CCH * P2 + pq;
    const float* w = Wc + c * CCH;
    for (int k = 0; k < CCH; ++k) acc += w[k] * I[k * P2];
    const float inv_area = (7.f * 7.f) / (32.f * 32.f);
    g_ctx[((size_t)b * CCH + c) * P2 + pq] = (acc + bc[c] * S) * inv_area;
}

// ---------------- K2c: K/L images, layout [img][s][pq][d] ----------------------
__global__ void k_KL(const float* __restrict__ Wof) {
    int b = blockIdx.x, s = blockIdx.y, pq = blockIdx.z;
    int d = threadIdx.x;
    float acc = 0.f;
    const float* w = Wof + d * 512 + 256 + s * 128;
    const float* x = g_ctx + ((size_t)b * CCH + s * 128) * P2 + pq;
    for (int k = 0; k < 128; ++k) acc += w[k] * x[k * P2];
    g_KL[((size_t)(b * 2 + s) * P2 + pq) * DD + d] = acc;
}

// ---------------- K6: A_sub/A_obj (fp16 out), layouts [roi][pq][d] -------------
__global__ void k_A(const float* __restrict__ Wrf) {
    int bi = blockIdx.x;
    int s = blockIdx.y;
    int d = threadIdx.x;
    __shared__ float Xs[64 * 49];   // [kl][pq]
    const float* X = g_objf + (size_t)bi * P2 * DD;   // [pq][k]
    const float* w = Wrf + d * 896 + s * 256;
    float acc[P2];
#pragma unroll
    for (int pq = 0; pq < P2; ++pq) acc[pq] = 0.f;
    for (int k0 = 0; k0 < 256; k0 += 64) {
        __syncthreads();
        for (int e = d; e < 64 * 49; e += 256) {
            int pq = e >> 6, kl = e & 63;
            Xs[kl * 49 + pq] = X[pq * 256 + k0 + kl];
        }
        __syncthreads();
        for (int kl = 0; kl < 64; ++kl) {
            float wv = w[k0 + kl];
            const float* xr = &Xs[kl * 49];
#pragma unroll
            for (int pq = 0; pq < P2; ++pq) acc[pq] += wv * xr[pq];
        }
    }
    __half* o = g_Ah + (((size_t)bi * 2 + s) * P2) * DD + d;
#pragma unroll
    for (int pq = 0; pq < P2; ++pq) o[(size_t)pq * DD] = __float2half(acc[pq]);
}

// ---------------- K7: pair assembly + relu, uint4 (8-half) vectorized -----------
// 128 threads: warp w owns pq = it*4 + w; lane covers 8 consecutive d.
__global__ void k_pair(const float* __restrict__ brf) {
    int bu = blockIdx.x;            // b*NU + u
    int b = bu / NU, u = bu - b * NU;
    int rem = u, i = 0;
    while (rem >= NO - i) { rem -= NO - i; ++i; }
    int j = i + rem;                // i <= j
    __shared__ float imA[P2], imB[P2];
    int tid = threadIdx.x;
    if (tid < P2) {
        imA[tid] = g_imap[((size_t)bu * 2 + 0) * P2 + tid];
        imB[tid] = g_imap[((size_t)bu * 2 + 1) * P2 + tid];
    }
    __syncthreads();
    int wp = tid >> 5, lane = tid & 31;
    const uint4* AiS = (const uint4*)(g_Ah + ((size_t)(b * NO + i) * 2 + 0) * P2 * DD);
    const uint4* AiO = (const uint4*)(g_Ah + ((size_t)(b * NO + i) * 2 + 1) * P2 * DD);
    const uint4* AjS = (const uint4*)(g_Ah + ((size_t)(b * NO + j) * 2 + 0) * P2 * DD);
    const uint4* AjO = (const uint4*)(g_Ah + ((size_t)(b * NO + j) * 2 + 1) * P2 * DD);
    const uint4* Pu  = (const uint4*)(g_Puh + (size_t)bu * P2 * 768);
    uint4* X0 = (uint4*)(g_Xh + (size_t)(b * NPAIR + i * NO + j) * KFC);
    uint4* X1 = (uint4*)(g_Xh + (size_t)(b * NPAIR + j * NO + i) * KFC);
    float bvv[8];
    *(float4*)&bvv[0] = *(const float4*)&brf[lane * 8];
    *(float4*)&bvv[4] = *(const float4*)&brf[lane * 8 + 4];
    bool diag = (i == j);
#pragma unroll 1
    for (int pq = wp; pq < P2; pq += 4) {
        float ia = imA[pq], ib = imB[pq];
        int pu0 = pq * 96 + lane;        // uint4 units (96 per Pu row)
        int ar = pq * 32 + lane;         // uint4 units (32 per 256-half row)
        uint4 xv = Pu[pu0];
        uint4 yv = Pu[pu0 + 32];
        uint4 zv = Pu[pu0 + 64];
        uint4 asv = AiS[ar];
        uint4 aov = AjO[ar];
        const __half2* xh = (const __half2*)&xv;
        const __half2* yh = (const __half2*)&yv;
        const __half2* zh = (const __half2*)&zv;
        const __half2* ash = (const __half2*)&asv;
        const __half2* aoh = (const __half2*)&aov;
        uint4 out0;
        __half2* oh0 = (__half2*)&out0;
#pragma unroll
        for (int c = 0; c < 4; ++c) {
            float2 x = __half22float2(xh[c]);
            float2 y = __half22float2(yh[c]);
            float2 z = __half22float2(zh[c]);
            float2 as = __half22float2(ash[c]);
            float2 ao = __half22float2(aoh[c]);
            float v0x = as.x + ao.x + x.x + ia * y.x + ib * z.x + bvv[c * 2];
            float v0y = as.y + ao.y + x.y + ia * y.y + ib * z.y + bvv[c * 2 + 1];
            oh0[c] = __floats2half2_rn(fmaxf(v0x, 0.f), fmaxf(v0y, 0.f));
        }
        X0[ar] = out0;
        if (!diag) {
            uint4 asv1 = AjS[ar];
            uint4 aov1 = AiO[ar];
            const __half2* ash1 = (const __half2*)&asv1;
            const __half2* aoh1 = (const __half2*)&aov1;
            uint4 out1;
            __half2* oh1 = (__half2*)&out1;
#pragma unroll
            for (int c = 0; c < 4; ++c) {
                float2 x = __half22float2(xh[c]);
                float2 y = __half22float2(yh[c]);
                float2 z = __half22float2(zh[c]);
                float2 as = __half22float2(ash1[c]);
                float2 ao = __half22float2(aoh1[c]);
                float v1x = as.x + ao.x + x.x + ib * y.x + ia * z.x + bvv[c * 2];
                float v1y = as.y + ao.y + x.y + ib * y.y + ia * z.y + bvv[c * 2 + 1];
                oh1[c] = __floats2half2_rn(fmaxf(v1x, 0.f), fmaxf(v1y, 0.f));
            }
            X1[ar] = out1;
        }
    }
}

// ---------------- weight permutations --------------------------------------------
__global__ void k_permWh(const float* __restrict__ W, __half* __restrict__ dst) {
    __shared__ float s[64 * 49];
    int dg = blockIdx.x;
    int n = blockIdx.y;
    int tid = threadIdx.x;
    const float* src = W + (size_t)n * KFC + dg * 64 * 49;
    for (int e = tid; e < 64 * 49; e += 256) s[e] = src[e];
    __syncthreads();
    __half* o = dst + (size_t)n * KFC + dg * 64;
    for (int e = tid; e < 64 * 49; e += 256) {
        int pq = e >> 6, dl = e & 63;
        o[(size_t)pq * 256 + dl] = __float2half(s[dl * 49 + pq]);
    }
}
__global__ void k_permW(const float* __restrict__ W, float* __restrict__ dst) {
    __shared__ float s[64 * 49];
    int dg = blockIdx.x;
    int n = blockIdx.y;
    int tid = threadIdx.x;
    const float* src = W + (size_t)n * KFC + dg * 64 * 49;
    for (int e = tid; e < 64 * 49; e += 256) s[e] = src[e];
    __syncthreads();
    float* o = dst + (size_t)n * KFC + dg * 64;
    for (int e = tid; e < 64 * 49; e += 256) {
        int pq = e >> 6, dl = e & 63;
        o[(size_t)pq * 256 + dl] = s[dl * 49 + pq];
    }
}

// ---------------- rel FC: TF32 MMA, A and B read from fp16, split-K ------------
__global__ __launch_bounds__(256) void k_fc_tf32(int M, int kchunk) {
    __shared__ unsigned As[16][136];
    __shared__ unsigned Bs[16][136];
    int m0 = blockIdx.x * 128, n0 = blockIdx.y * 128, z = blockIdx.z;
    int kb = z * kchunk;
    int tid = threadIdx.x;
    int row = tid >> 1, kq = (tid & 1) * 8;
    const __half* Ap = g_Xh + (size_t)(m0 + row) * KFC + kb + kq;
    const __half* Bp = g_Wph + (size_t)(n0 + row) * KFC + kb + kq;
    int lane = tid & 31;
    int g = lane >> 2, tg = lane & 3;
    int warp = tid >> 5;
    int wm = (warp & 3) * 32, wn = (warp >> 2) * 64;

    float acc[2][8][4];
#pragma unroll
    for (int mi = 0; mi < 2; ++mi)
#pragma unroll
        for (int nj = 0; nj < 8; ++nj)
#pragma unroll
            for (int r = 0; r < 4; ++r) acc[mi][nj][r] = 0.f;

    uint4 rah = *(const uint4*)(Ap);
    uint4 rbh = *(const uint4*)(Bp);

    for (int k0 = 0; k0 < kchunk; k0 += 16) {
        {
            float2 f0 = __half22float2(*(__half2*)&rah.x), f1 = __half22float2(*(__half2*)&rah.y);
            float2 f2 = __half22float2(*(__half2*)&rah.z), f3 = __half22float2(*(__half2*)&rah.w);
            As[kq + 0][row] = f2tf32(f0.x); As[kq + 1][row] = f2tf32(f0.y);
            As[kq + 2][row] = f2tf32(f1.x); As[kq + 3][row] = f2tf32(f1.y);
            As[kq + 4][row] = f2tf32(f2.x); As[kq + 5][row] = f2tf32(f2.y);
            As[kq + 6][row] = f2tf32(f3.x); As[kq + 7][row] = f2tf32(f3.y);
        }
        {
            float2 f0 = __half22float2(*(__half2*)&rbh.x), f1 = __half22float2(*(__half2*)&rbh.y);
            float2 f2 = __half22float2(*(__half2*)&rbh.z), f3 = __half22float2(*(__half2*)&rbh.w);
            Bs[kq + 0][row] = f2tf32(f0.x); Bs[kq + 1][row] = f2tf32(f0.y);
            Bs[kq + 2][row] = f2tf32(f1.x); Bs[kq + 3][row] = f2tf32(f1.y);
            Bs[kq + 4][row] = f2tf32(f2.x); Bs[kq + 5][row] = f2tf32(f2.y);
            Bs[kq + 6][row] = f2tf32(f3.x); Bs[kq + 7][row] = f2tf32(f3.y);
        }
        __syncthreads();
        int kn = k0 + 16;
        if (kn < kchunk) {
            rah = *(const uint4*)(Ap + kn);
            rbh = *(const uint4*)(Bp + kn);
        }
#pragma unroll
        for (int kk = 0; kk < 16; kk += 8) {
            unsigned af[2][4];
#pragma unroll
            for (int mi = 0; mi < 2; ++mi) {
                int mb = wm + mi * 16;
                af[mi][0] = As[kk + tg][mb + g];
                af[mi][1] = As[kk + tg][mb + g + 8];
                af[mi][2] = As[kk + tg + 4][mb + g];
                af[mi][3] = As[kk + tg + 4][mb + g + 8];
            }
            unsigned bf[8][2];
#pragma unroll
            for (int nj = 0; nj < 8; ++nj) {
                bf[nj][0] = Bs[kk + tg][wn + nj * 8 + g];
                bf[nj][1] = Bs[kk + tg + 4][wn + nj * 8 + g];
            }
#pragma unroll
            for (int mi = 0; mi < 2; ++mi)
#pragma unroll
                for (int nj = 0; nj < 8; ++nj) {
                    asm volatile(
                        "mma.sync.aligned.m16n8k8.row.col.f32.tf32.tf32.f32 "
                        "{%0,%1,%2,%3},{%4,%5,%6,%7},{%8,%9},{%0,%1,%2,%3};"
                        : "+f"(acc[mi][nj][0]), "+f"(acc[mi][nj][1]),
                          "+f"(acc[mi][nj][2]), "+f"(acc[mi][nj][3])
                        : "r"(af[mi][0]), "r"(af[mi][1]), "r"(af[mi][2]), "r"(af[mi][3]),
                          "r"(bf[nj][0]), "r"(bf[nj][1]));
                }
        }
        __syncthreads();
    }
#pragma unroll
    for (int mi = 0; mi < 2; ++mi) {
        int m = m0 + wm + mi * 16 + g;
#pragma unroll
        for (int nj = 0; nj < 8; ++nj) {
            int n = n0 + wn + nj * 8 + 2 * tg;
            float* p0 = &g_part[((size_t)z * M + m) * 256 + n];
            float* p1 = &g_part[((size_t)z * M + m + 8) * 256 + n];
            *(float2*)p0 = make_float2(acc[mi][nj][0], acc[mi][nj][1]);
            *(float2*)p1 = make_float2(acc[mi][nj][2], acc[mi][nj][3]);
        }
    }
}

// ---------------- obj FC: fp32 SIMT, split-K, relu at load ----------------------
__global__ __launch_bounds__(256) void k_fc2(const float* __restrict__ W,
                                             int M, int kchunk) {
    __shared__ float As[16][128];
    __shared__ float Bs[16][128];
    const float* A = (const float*)g_objf;
    int m0 = blockIdx.x * 128, n0 = blockIdx.y * 128, z = blockIdx.z;
    int kb = z * kchunk;
    int tid = threadIdx.x;
    int tx = tid & 15, ty = tid >> 4;
    int arow = tid >> 1, akq = (tid & 1) * 8;
    const float* Ap = A + (size_t)(m0 + arow) * KFC + kb;
    const float* Bp = W + (size_t)(n0 + arow) * KFC + kb;
    float4 ra0 = *(const float4*)(Ap + akq);
    float4 ra1 = *(const float4*)(Ap + akq + 4);
    float4 rb0 = *(const float4*)(Bp + akq);
    float4 rb1 = *(const float4*)(Bp + akq + 4);
    float acc[8][8] = {};
    for (int k0 = 0; k0 < kchunk; k0 += 16) {
        ra0.x = fmaxf(ra0.x, 0.f); ra0.y = fmaxf(ra0.y, 0.f);
        ra0.z = fmaxf(ra0.z, 0.f); ra0.w = fmaxf(ra0.w, 0.f);
        ra1.x = fmaxf(ra1.x, 0.f); ra1.y = fmaxf(ra1.y, 0.f);
        ra1.z = fmaxf(ra1.z, 0.f); ra1.w = fmaxf(ra1.w, 0.f);
        As[akq + 0][arow] = ra0.x; As[akq + 1][arow] = ra0.y;
        As[akq + 2][arow] = ra0.z; As[akq + 3][arow] = ra0.w;
        As[akq + 4][arow] = ra1.x; As[akq + 5][arow] = ra1.y;
        As[akq + 6][arow] = ra1.z; As[akq + 7][arow] = ra1.w;
        Bs[akq + 0][arow] = rb0.x; Bs[akq + 1][arow] = rb0.y;
        Bs[akq + 2][arow] = rb0.z; Bs[akq + 3][arow] = rb0.w;
        Bs[akq + 4][arow] = rb1.x; Bs[akq + 5][arow] = rb1.y;
        Bs[akq + 6][arow] = rb1.z; Bs[akq + 7][arow] = rb1.w;
        __syncthreads();
        int kn = k0 + 16;
        if (kn < kchunk) {
            ra0 = *(const float4*)(Ap + kn + akq);
            ra1 = *(const float4*)(Ap + kn + akq + 4);
            rb0 = *(const float4*)(Bp + kn + akq);
            rb1 = *(const float4*)(Bp + kn + akq + 4);
        }
#pragma unroll
        for (int kk = 0; kk < 16; ++kk) {
            float4 a0 = *(const float4*)&As[kk][ty * 8];
            float4 a1 = *(const float4*)&As[kk][ty * 8 + 4];
            float4 b0 = *(const float4*)&Bs[kk][tx * 8];
            float4 b1 = *(const float4*)&Bs[kk][tx * 8 + 4];
            float av[8] = {a0.x, a0.y, a0.z, a0.w, a1.x, a1.y, a1.z, a1.w};
            float bv[8] = {b0.x, b0.y, b0.z, b0.w, b1.x, b1.y, b1.z, b1.w};
#pragma unroll
            for (int i = 0; i < 8; ++i)
#pragma unroll
                for (int j = 0; j < 8; ++j) acc[i][j] += av[i] * bv[j];
        }
        __syncthreads();
    }
#pragma unroll
    for (int i = 0; i < 8; ++i) {
        int m = m0 + ty * 8 + i;
        float* o = &g_part[((size_t)z * M + m) * 256 + n0 + tx * 8];
        *(float4*)o       = make_float4(acc[i][0], acc[i][1], acc[i][2], acc[i][3]);
        *(float4*)(o + 4) = make_float4(acc[i][4], acc[i][5], acc[i][6], acc[i][7]);
    }
}

// reduce split-K partials + bias
__global__ void k_reduce(int which, const float* __restrict__ bias, int M, int Z) {
    int idx = blockIdx.x * 256 + threadIdx.x;
    if (idx >= M * 256) return;
    float s = bias[idx & 255];
    for (int z = 0; z < Z; ++z) s += g_part[(size_t)z * M * 256 + idx];
    if (which) g_O[idx] = s; else g_R[idx] = s;
}

// ---------------- K10: L2 normalize ---------------------------------------------
__global__ void k_norm(float* __restrict__ dst, int which) {
    int r = blockIdx.x, tid = threadIdx.x;
    const float* src = which ? (const float*)g_R : (const float*)g_O;
    float v = src[(size_t)r * DD + tid];
    float s = v * v;
#pragma unroll
    for (int o = 16; o > 0; o >>= 1) s += __shfl_xor_sync(0xffffffffu, s, o);
    __shared__ float ws[8];
    if ((tid & 31) == 0) ws[tid >> 5] = s;
    __syncthreads();
    float tot = 0.f;
#pragma unroll
    for (int k = 0; k < 8; ++k) tot += ws[k];
    dst[(size_t)r * DD + tid] = v * rsqrtf(tot);
}

// ---------------- launch ----------------------------------------------------------
extern "C" void kernel_launch(void* const* d_in, const int* in_sizes, int n_in,
                              void* d_out, int out_size) {
    const float* input   = (const float*)d_in[0];
    const float* objects = (const float*)d_in[1];
    const float* Wc   = (const float*)d_in[3];
    const float* bc   = (const float*)d_in[4];
    const float* Wr   = (const float*)d_in[5];
    const float* br   = (const float*)d_in[6];
    const float* Wof  = (const float*)d_in[7];
    const float* bof  = (const float*)d_in[8];
    const float* Wrf  = (const float*)d_in[9];
    const float* brf  = (const float*)d_in[10];
    const float* Wofc = (const float*)d_in[11];
    const float* bofc = (const float*)d_in[12];
    const float* Wrfc = (const float*)d_in[13];
    const float* brfc = (const float*)d_in[14];
    float* out = (float*)d_out;

    __half* wph; cudaGetSymbolAddress((void**)&wph, g_Wph);
    float* wp2;  cudaGetSymbolAddress((void**)&wp2, g_Wp2);

    k_combine<<<1024, 256>>>(Wof, Wrf, Wr, br);
    k_geom<<<8, 256>>>(objects);
    k_pool0<<<dim3(8, 8), 224>>>(input);                                 // I0 raw
    k_projT_mma<<<dim3(8, 8, 8), 256>>>(input);                          // <-- profiled (TF32 MMA)
    k_poolT<<<dim3(1088, 3), 256>>>(nullptr, 2, NU, nullptr);            // union pool
    k_ctx<<<dim3(8, 49), 256>>>(Wc, bc);
    k_KL<<<dim3(8, 2, 49), 256>>>(Wof);
    k_poolT<<<dim3(128, 1), 256>>>(objects, 1, NO, bof);                 // obj pool + epi
    k_A<<<dim3(128, 2), 256>>>(Wrf);
    k_pair<<<1088, 128>>>(brf);
    k_permWh<<<dim3(4, 256), 256>>>(Wrfc, wph);
    k_fc_tf32<<<dim3(16, 2, 8), 256>>>(2048, 1568);                      // rel FC (TF32, fp16 A+B)
    k_reduce<<<2048, 256>>>(0, brfc, 2048, 8);
    k_permW<<<dim3(4, 256), 256>>>(Wofc, wp2);
    k_fc2<<<dim3(1, 2, 16), 256>>>(wp2, 128, 784);                       // obj FC
    k_reduce<<<128, 256>>>(1, bofc, 128, 16);
    k_norm<<<128, 256>>>(out, 0);                                        // obj_out
    k_norm<<<2048, 256>>>(out + 32768, 1);                               // rel_out
    (void)in_sizes; (void)n_in; (void)out_size;
}